// round 12
// baseline (speedup 1.0000x reference)
#include <cuda_runtime.h>
#include <cuda_bf16.h>
#include <cstdint>

#define NPTS 4096
#define KNB  32
#define BMAX 4

typedef unsigned long long ull;

// ---------------- f32x2 helpers (feat kernel) ----------------
__device__ __forceinline__ ull pack2(float lo, float hi) {
    ull r; asm("mov.b64 %0, {%1, %2};" : "=l"(r) : "f"(lo), "f"(hi)); return r;
}
__device__ __forceinline__ ull ffma2(ull a, ull b, ull c) {
    ull d; asm("fma.rn.f32x2 %0, %1, %2, %3;" : "=l"(d) : "l"(a), "l"(b), "l"(c));
    return d;
}
__device__ __forceinline__ float2 unpack2(ull v) {
    float lo, hi; asm("mov.b64 {%0, %1}, %2;" : "=f"(lo), "=f"(hi) : "l"(v));
    return make_float2(lo, hi);
}

// ---------------- bf16 split + mma helpers ----------------
// 4 fp32 -> 2 packed bf16x2 hi + 2 lo
__device__ __forceinline__ void cvt_split4(const float* v, uint32_t* h, uint32_t* l) {
#pragma unroll
    for (int j = 0; j < 2; j++) {
        uint32_t hh;
        asm("cvt.rn.bf16x2.f32 %0, %1, %2;" : "=r"(hh) : "f"(v[2 * j + 1]), "f"(v[2 * j]));
        const float f0 = __uint_as_float(hh << 16);
        const float f1 = __uint_as_float(hh & 0xFFFF0000u);
        uint32_t ll;
        asm("cvt.rn.bf16x2.f32 %0, %1, %2;" : "=r"(ll)
            : "f"(v[2 * j + 1] - f1), "f"(v[2 * j] - f0));
        h[j] = hh; l[j] = ll;
    }
}
__device__ __forceinline__ void mma_bf16(float* c, const uint32_t* a, const uint32_t* b) {
    asm volatile(
        "mma.sync.aligned.m16n8k16.row.col.f32.bf16.bf16.f32 "
        "{%0,%1,%2,%3}, {%4,%5,%6,%7}, {%8,%9}, {%0,%1,%2,%3};"
        : "+f"(c[0]), "+f"(c[1]), "+f"(c[2]), "+f"(c[3])
        : "r"(a[0]), "r"(a[1]), "r"(a[2]), "r"(a[3]), "r"(b[0]), "r"(b[1]));
}
__device__ __forceinline__ void ldsm4(uint32_t& r0, uint32_t& r1, uint32_t& r2, uint32_t& r3,
                                      uint32_t addr) {
    asm volatile("ldmatrix.sync.aligned.m8n8.x4.shared.b16 {%0,%1,%2,%3}, [%4];"
                 : "=r"(r0), "=r"(r1), "=r"(r2), "=r"(r3) : "r"(addr));
}
__device__ __forceinline__ uint32_t smem_u32(const void* p) {
    uint32_t a;
    asm("{ .reg .u64 t; cvta.to.shared.u64 t, %1; cvt.u32.u64 %0, t; }" : "=r"(a) : "l"(p));
    return a;
}
__device__ __forceinline__ void cp16(uint32_t dst, const void* src) {
    asm volatile("cp.async.ca.shared.global [%0], [%1], 16;" :: "r"(dst), "l"(src));
}

// ---------------- scratch ----------------
__device__ __align__(16) int            g_idx    [BMAX * NPTS * KNB];
__device__ __align__(16) float          g_feat   [(size_t)3 * BMAX * NPTS * 128];
__device__ __align__(16) __nv_bfloat16  g_pt_h   [(size_t)BMAX * NPTS * 384];
__device__ __align__(16) __nv_bfloat16  g_pt_l   [(size_t)BMAX * NPTS * 384];
__device__ __align__(16) __nv_bfloat16  g_gf0_h  [(size_t)BMAX * NPTS * 256];
__device__ __align__(16) __nv_bfloat16  g_gf0_l  [(size_t)BMAX * NPTS * 256];
__device__ __align__(16) __nv_bfloat16  g_gf_h   [(size_t)BMAX * NPTS * 1024];
__device__ __align__(16) __nv_bfloat16  g_gf_l   [(size_t)BMAX * NPTS * 1024];
__device__ __align__(16) __nv_bfloat16  g_msf0_h [(size_t)BMAX * NPTS * 256];
__device__ __align__(16) __nv_bfloat16  g_msf0_l [(size_t)BMAX * NPTS * 256];
__device__ __align__(16) float          g_msf_t  [(size_t)BMAX * NPTS * 128];
__device__ __align__(16) float          g_part   [BMAX * 16 * 1024];
// weights, concatenated: gW0(98304) | gW1(262144) | mW0(262144) | mW1(32768)
__device__ __align__(16) __nv_bfloat16  g_w_h    [655360];
__device__ __align__(16) __nv_bfloat16  g_w_l    [655360];

// =================================================================
// K0: split fp32 -> bf16 hi/lo (weights)
// =================================================================
__global__ __launch_bounds__(256) void split_kernel(const float* __restrict__ in,
                                                    __nv_bfloat16* __restrict__ h,
                                                    __nv_bfloat16* __restrict__ l, int n)
{
    const int i = (blockIdx.x * 256 + threadIdx.x) * 4;
    if (i >= n) return;
    const float4 v = *(const float4*)(in + i);
    uint32_t hh[2], ll[2];
    cvt_split4(&v.x, hh, ll);
    *(uint2*)(h + i) = make_uint2(hh[0], hh[1]);
    *(uint2*)(l + i) = make_uint2(ll[0], ll[1]);
}

// =================================================================
// K1: KNN — warp per query, lane-distributed sorted top-32 list
// =================================================================
__global__ __launch_bounds__(256) void knn_kernel(const float* __restrict__ x,
                                                  int* __restrict__ idx)
{
    __shared__ float4 tile[1024];
    const int b = blockIdx.y;
    const int tid = threadIdx.x;
    const int w = tid >> 5, lane = tid & 31;
    const int q = blockIdx.x * 8 + w;
    const float* xb = x + (size_t)b * 3 * NPTS;

    const float qx = xb[q], qy = xb[NPTS + q], qz = xb[2 * NPTS + q];
    const float qsq = qx * qx + qy * qy + qz * qz;

    float v = 3.0e38f;
    int   vi = 0x7fffffff;
    float cm = 3.0e38f;

    for (int t0 = 0; t0 < NPTS; t0 += 1024) {
        __syncthreads();
        for (int i = tid; i < 1024; i += 256) {
            const int g = t0 + i;
            const float cx = xb[g], cy = xb[NPTS + g], cz = xb[2 * NPTS + g];
            tile[i] = make_float4(cx, cy, cz, cx * cx + cy * cy + cz * cz);
        }
        __syncthreads();

        for (int c = 0; c < 32; c++) {
            const int gbase = t0 + c * 32;
            const float4 p = tile[c * 32 + lane];
            float d = qsq + p.w - 2.0f * fmaf(qx, p.x, fmaf(qy, p.y, qz * p.z));
            if (gbase + lane == q) d = 3.0e38f;

            unsigned m = __ballot_sync(0xffffffffu, d < cm);
            while (m) {
                const int src = __ffs(m) - 1; m &= m - 1;
                const float dd = __shfl_sync(0xffffffffu, d, src);
                const int   ii = gbase + src;
                const unsigned less = __ballot_sync(0xffffffffu,
                        (v < dd) || (v == dd && vi < ii));
                const int pos = __popc(less);
                const float pv = __shfl_up_sync(0xffffffffu, v, 1);
                const int   pi = __shfl_up_sync(0xffffffffu, vi, 1);
                if (pos < 32) {
                    if (lane == pos)      { v = dd; vi = ii; }
                    else if (lane > pos)  { v = pv; vi = pi; }
                }
                cm = __shfl_sync(0xffffffffu, v, 31);
            }
        }
    }
    idx[((size_t)b * NPTS + q) * KNB + lane] = vi;
}

// =================================================================
// K2: per-point 3-layer MLP (3->64->64->128), f32x2 packed math.
// =================================================================
#define SMEM_FEAT_FLOATS (192 + 64 + 4096 + 64 + 8192 + 128)
#define SMEM_FEAT_BYTES  (SMEM_FEAT_FLOATS * 4)

__global__ __launch_bounds__(128) void feat_kernel(
    const float* __restrict__ x,
    const float* __restrict__ sW0, const float* __restrict__ sb0,
    const float* __restrict__ sW1, const float* __restrict__ sb1,
    const float* __restrict__ sW2, const float* __restrict__ sb2,
    float* __restrict__ feat, int B)
{
    extern __shared__ float sm[];
    float* w0s = sm;
    float* b0s = w0s + 192;
    float* w1s = b0s + 64;
    float* b1s = w1s + 4096;
    float* w2s = b1s + 64;
    float* b2s = w2s + 8192;

    const int s = blockIdx.y, b = blockIdx.z;
    const int tid = threadIdx.x;

    for (int i = tid; i < 192;  i += 128) w0s[i] = sW0[s * 192 + i];
    for (int i = tid; i < 64;   i += 128) { b0s[i] = sb0[s * 64 + i]; b1s[i] = sb1[s * 64 + i]; }
    for (int i = tid; i < 4096; i += 128) w1s[i] = sW1[s * 4096 + i];
    for (int i = tid; i < 8192; i += 128) w2s[i] = sW2[s * 8192 + i];
    for (int i = tid; i < 128;  i += 128) b2s[i] = sb2[s * 128 + i];
    __syncthreads();

    const int j = blockIdx.x * 128 + tid;
    const float* xb = x + (size_t)b * 3 * NPTS;
    const float px = xb[j], py = xb[NPTS + j], pz = xb[2 * NPTS + j];

    float h0[64];
#pragma unroll
    for (int o = 0; o < 64; o++) {
        float a = fmaf(w0s[o * 3 + 2], pz,
                  fmaf(w0s[o * 3 + 1], py,
                  fmaf(w0s[o * 3 + 0], px, b0s[o])));
        h0[o] = fmaxf(a, 0.0f);
    }

    ull hp[32];
#pragma unroll
    for (int c = 0; c < 32; c++) hp[c] = pack2(h0[2 * c], h0[2 * c + 1]);

    float h1[64];
#pragma unroll
    for (int o = 0; o < 64; o += 2) {
        ull a0 = 0ull, a1 = 0ull;
        const ull* r0 = (const ull*)(w1s + (o    ) * 64);
        const ull* r1 = (const ull*)(w1s + (o + 1) * 64);
#pragma unroll
        for (int c = 0; c < 32; c++) {
            a0 = ffma2(r0[c], hp[c], a0);
            a1 = ffma2(r1[c], hp[c], a1);
        }
        const float2 u0 = unpack2(a0), u1 = unpack2(a1);
        h1[o]     = fmaxf(u0.x + u0.y + b1s[o],     0.0f);
        h1[o + 1] = fmaxf(u1.x + u1.y + b1s[o + 1], 0.0f);
    }

#pragma unroll
    for (int c = 0; c < 32; c++) hp[c] = pack2(h1[2 * c], h1[2 * c + 1]);

    float* fout = feat + ((size_t)(s * B + b) * NPTS + j) * 128;
    for (int o = 0; o < 128; o += 4) {
        ull a0 = 0ull, a1 = 0ull, a2 = 0ull, a3 = 0ull;
        const ull* r0 = (const ull*)(w2s + (size_t)(o    ) * 64);
        const ull* r1 = (const ull*)(w2s + (size_t)(o + 1) * 64);
        const ull* r2 = (const ull*)(w2s + (size_t)(o + 2) * 64);
        const ull* r3 = (const ull*)(w2s + (size_t)(o + 3) * 64);
#pragma unroll
        for (int c = 0; c < 32; c++) {
            a0 = ffma2(r0[c], hp[c], a0);
            a1 = ffma2(r1[c], hp[c], a1);
            a2 = ffma2(r2[c], hp[c], a2);
            a3 = ffma2(r3[c], hp[c], a3);
        }
        const float2 u0 = unpack2(a0), u1 = unpack2(a1);
        const float2 u2 = unpack2(a2), u3 = unpack2(a3);
        float4 o4;
        o4.x = fmaxf(u0.x + u0.y + b2s[o],     0.0f);
        o4.y = fmaxf(u1.x + u1.y + b2s[o + 1], 0.0f);
        o4.z = fmaxf(u2.x + u2.y + b2s[o + 2], 0.0f);
        o4.w = fmaxf(u3.x + u3.y + b2s[o + 3], 0.0f);
        *(float4*)(fout + o) = o4;
    }
}

// =================================================================
// K3: gather-max over 32 neighbors -> point planes (bf16 hi/lo)
// =================================================================
__global__ __launch_bounds__(256) void maxpool_kernel(
    const float* __restrict__ feat, const int* __restrict__ idx,
    __nv_bfloat16* __restrict__ pt_h, __nv_bfloat16* __restrict__ pt_l, int B)
{
    const int s = blockIdx.y, b = blockIdx.z;
    const int tid = threadIdx.x;
    const int w = tid >> 5, lane = tid & 31;
    const int n = blockIdx.x * 8 + w;

    const int ki = idx[((size_t)b * NPTS + n) * KNB + lane];
    const float* fb = feat + (size_t)(s * B + b) * NPTS * 128;

    float4 m = make_float4(-3.0e38f, -3.0e38f, -3.0e38f, -3.0e38f);
#pragma unroll
    for (int k = 0; k < KNB; k++) {
        const int j = __shfl_sync(0xffffffffu, ki, k);
        const float4 vv = *(const float4*)(fb + (size_t)j * 128 + lane * 4);
        m.x = fmaxf(m.x, vv.x); m.y = fmaxf(m.y, vv.y);
        m.z = fmaxf(m.z, vv.z); m.w = fmaxf(m.w, vv.w);
    }
    uint32_t h[2], l[2];
    cvt_split4(&m.x, h, l);
    const size_t ofs = ((size_t)b * NPTS + n) * 384 + s * 128 + lane * 4;
    *(uint2*)(pt_h + ofs) = make_uint2(h[0], h[1]);
    *(uint2*)(pt_l + ofs) = make_uint2(l[0], l[1]);
}

// =================================================================
// K4: mma.sync bf16 GEMM on pre-split hi/lo planes, cp.async loads.
// Y = relu(W @ X^T + bias); outputs bf16 planes (and fp32 if Yf).
// CTA 128x128, 8 warps (2M x 4N, warp 64x32), k-chunk 32, 2-stage.
// smem rows [dim][k] bf16, pitch 80 B; LDSM conflict-free.
// =================================================================
#define KCH    32
#define PITCH  80                        // bytes per row (64 data + 16 pad)
#define TILEB  (128 * PITCH)             // 10240 B per tile
#define STG_B  (4 * TILEB)               // Ah|Al|Bh|Bl per stage
#define SMEM_GEMM_BYTES (2 * STG_B)      // 81920

__global__ __launch_bounds__(256, 2) void gemm_mma(
    const __nv_bfloat16* __restrict__ Wh, const __nv_bfloat16* __restrict__ Wl,
    const float* __restrict__ bias,
    const __nv_bfloat16* __restrict__ Xh, const __nv_bfloat16* __restrict__ Xl,
    __nv_bfloat16* __restrict__ Yh, __nv_bfloat16* __restrict__ Yl,
    float* __restrict__ Yf, int M, int K)
{
    extern __shared__ __align__(16) char smem[];
    const uint32_t sb = smem_u32(smem);

    const int tid = threadIdx.x, wid = tid >> 5, lane = tid & 31;
    const int wm = wid & 1, wn = wid >> 1;
    const int m0 = blockIdx.x * 128, n0 = blockIdx.y * 128;
    const int bi = blockIdx.z;
    const size_t xrow0 = (size_t)bi * NPTS + n0;

    const uint32_t aOff = (uint32_t)(wm * 64 + (lane & 7) + ((lane >> 3) & 1) * 8) * PITCH
                        + ((lane >> 4) & 1) * 16;
    const uint32_t bOff = (uint32_t)(wn * 32 + (lane & 7) + ((lane >> 4) & 1) * 8) * PITCH
                        + ((lane >> 3) & 1) * 16;

    float acc[4][4][4];
#pragma unroll
    for (int i = 0; i < 4; i++)
#pragma unroll
        for (int j = 0; j < 4; j++)
#pragma unroll
            for (int r = 0; r < 4; r++) acc[i][j][r] = 0.0f;

    const int nch = K / KCH;

    // cp.async issue of one chunk into stage stg
    auto issue = [&](int ch, int stg) {
        const uint32_t sbase = sb + (uint32_t)stg * STG_B;
        const int kof = ch * KCH;
#pragma unroll
        for (int r = 0; r < 2; r++) {
            const int unit = tid + r * 256;          // 0..511
            const int row = unit >> 2, seg = unit & 3;
            const uint32_t d = sbase + (uint32_t)row * PITCH + seg * 16;
            const size_t aidx = (size_t)(m0 + row) * K + kof + seg * 8;
            const size_t bidx = (xrow0 + row) * K + kof + seg * 8;
            cp16(d,             Wh + aidx);
            cp16(d + TILEB,     Wl + aidx);
            cp16(d + 2 * TILEB, Xh + bidx);
            cp16(d + 3 * TILEB, Xl + bidx);
        }
        asm volatile("cp.async.commit_group;" ::: "memory");
    };

    issue(0, 0);

    for (int ch = 0; ch < nch; ch++) {
        const int cur = ch & 1;
        const bool more = (ch + 1 < nch);
        if (more) issue(ch + 1, cur ^ 1);
        if (more) asm volatile("cp.async.wait_group 1;" ::: "memory");
        else      asm volatile("cp.async.wait_group 0;" ::: "memory");
        __syncthreads();

        const uint32_t aT = sb + (uint32_t)cur * STG_B + aOff;
        const uint32_t bT = sb + (uint32_t)cur * STG_B + 2 * TILEB + bOff;
#pragma unroll
        for (int ks = 0; ks < 2; ks++) {
            const uint32_t kso = ks * 32;
            uint32_t bh[4][2], bl[4][2];
            ldsm4(bh[0][0], bh[0][1], bh[1][0], bh[1][1], bT + kso);
            ldsm4(bh[2][0], bh[2][1], bh[3][0], bh[3][1], bT + 16 * PITCH + kso);
            ldsm4(bl[0][0], bl[0][1], bl[1][0], bl[1][1], bT + TILEB + kso);
            ldsm4(bl[2][0], bl[2][1], bl[3][0], bl[3][1], bT + TILEB + 16 * PITCH + kso);
#pragma unroll
            for (int mih = 0; mih < 2; mih++) {
                uint32_t ah[2][4], al[2][4];
#pragma unroll
                for (int mi2 = 0; mi2 < 2; mi2++) {
                    const uint32_t ao = aT + (uint32_t)(mih * 2 + mi2) * (16 * PITCH) + kso;
                    ldsm4(ah[mi2][0], ah[mi2][1], ah[mi2][2], ah[mi2][3], ao);
                    ldsm4(al[mi2][0], al[mi2][1], al[mi2][2], al[mi2][3], ao + TILEB);
                }
#pragma unroll
                for (int mi2 = 0; mi2 < 2; mi2++)
#pragma unroll
                    for (int ni = 0; ni < 4; ni++) {
                        float* c = acc[mih * 2 + mi2][ni];
                        mma_bf16(c, ah[mi2], bh[ni]);
                        mma_bf16(c, ah[mi2], bl[ni]);
                        mma_bf16(c, al[mi2], bh[ni]);
                    }
            }
        }
        __syncthreads();   // all reads of cur done before it is overwritten
    }

    // epilogue: c0:(g, 2t) c1:(g, 2t+1) c2:(g+8, 2t) c3:(g+8, 2t+1)
    const int g = lane >> 2, t2 = (lane & 3) * 2;
#pragma unroll
    for (int mi = 0; mi < 4; mi++) {
        const int mlo = m0 + wm * 64 + mi * 16 + g;
        const float bv0 = bias[mlo], bv1 = bias[mlo + 8];
#pragma unroll
        for (int ni = 0; ni < 4; ni++) {
            const int n = n0 + wn * 32 + ni * 8 + t2;
            const size_t r0 = ((size_t)bi * NPTS + n) * M;
            const size_t r1 = r0 + M;
            float vv[4];
            vv[0] = fmaxf(acc[mi][ni][0] + bv0, 0.0f);
            vv[1] = fmaxf(acc[mi][ni][1] + bv0, 0.0f);
            vv[2] = fmaxf(acc[mi][ni][2] + bv1, 0.0f);
            vv[3] = fmaxf(acc[mi][ni][3] + bv1, 0.0f);
            if (Yh) {
#pragma unroll
                for (int q = 0; q < 4; q++) {
                    const size_t o = (q & 1 ? r1 : r0) + mlo + (q >> 1) * 8;
                    const __nv_bfloat16 hb = __float2bfloat16(vv[q]);
                    Yh[o] = hb;
                    Yl[o] = __float2bfloat16(vv[q] - __bfloat162float(hb));
                }
            }
            if (Yf) {
                Yf[r0 + mlo]     = vv[0];
                Yf[r1 + mlo]     = vv[1];
                Yf[r0 + mlo + 8] = vv[2];
                Yf[r1 + mlo + 8] = vv[3];
            }
        }
    }
}

// =================================================================
// rowmax on gf planes (hi+lo), two-phase
// =================================================================
__global__ __launch_bounds__(256) void rowmax_part(const __nv_bfloat16* __restrict__ gh,
                                                   const __nv_bfloat16* __restrict__ gl,
                                                   float* __restrict__ part)
{
    const int c = blockIdx.x * 256 + threadIdx.x;
    const int ns = blockIdx.y, b = blockIdx.z;
    const size_t base = ((size_t)b * NPTS + ns * 256) * 1024 + c;
    float m0 = -3.0e38f, m1 = -3.0e38f, m2 = -3.0e38f, m3 = -3.0e38f;
#pragma unroll 4
    for (int n = 0; n < 256; n += 4) {
        m0 = fmaxf(m0, __bfloat162float(gh[base + (size_t)(n    ) * 1024]) +
                       __bfloat162float(gl[base + (size_t)(n    ) * 1024]));
        m1 = fmaxf(m1, __bfloat162float(gh[base + (size_t)(n + 1) * 1024]) +
                       __bfloat162float(gl[base + (size_t)(n + 1) * 1024]));
        m2 = fmaxf(m2, __bfloat162float(gh[base + (size_t)(n + 2) * 1024]) +
                       __bfloat162float(gl[base + (size_t)(n + 2) * 1024]));
        m3 = fmaxf(m3, __bfloat162float(gh[base + (size_t)(n + 3) * 1024]) +
                       __bfloat162float(gl[base + (size_t)(n + 3) * 1024]));
    }
    part[(size_t)(b * 16 + ns) * 1024 + c] = fmaxf(fmaxf(m0, m1), fmaxf(m2, m3));
}

__global__ __launch_bounds__(256) void rowmax_fin(const float* __restrict__ part,
                                                  float* __restrict__ out)
{
    const int c = blockIdx.x * 256 + threadIdx.x;
    const int b = blockIdx.y;
    float m = -3.0e38f;
#pragma unroll
    for (int i = 0; i < 16; i++)
        m = fmaxf(m, part[(size_t)(b * 16 + i) * 1024 + c]);
    out[(size_t)b * 1024 + c] = m;
}

// =================================================================
// transpose msf_t[b][n][128] -> out[b][128][n]
// =================================================================
__global__ void transpose_msf(const float* __restrict__ in, float* __restrict__ out)
{
    __shared__ float t[32][33];
    const int b = blockIdx.z;
    const int n0 = blockIdx.x * 32, c0 = blockIdx.y * 32;
    const int tx = threadIdx.x, ty = threadIdx.y;   // 32 x 8
#pragma unroll
    for (int r = 0; r < 32; r += 8)
        t[ty + r][tx] = in[(size_t)((size_t)b * NPTS + n0 + ty + r) * 128 + c0 + tx];
    __syncthreads();
#pragma unroll
    for (int r = 0; r < 32; r += 8)
        out[(size_t)((size_t)b * 128 + c0 + ty + r) * NPTS + n0 + tx] = t[tx][ty + r];
}

// =================================================================
extern "C" void kernel_launch(void* const* d_in, const int* in_sizes, int n_in,
                              void* d_out, int out_size)
{
    const float* x   = (const float*)d_in[0];
    const float* sW0 = (const float*)d_in[1];
    const float* sb0 = (const float*)d_in[2];
    const float* sW1 = (const float*)d_in[3];
    const float* sb1 = (const float*)d_in[4];
    const float* sW2 = (const float*)d_in[5];
    const float* sb2 = (const float*)d_in[6];
    const float* gW0 = (const float*)d_in[7];
    const float* gb0 = (const float*)d_in[8];
    const float* gW1 = (const float*)d_in[9];
    const float* gb1 = (const float*)d_in[10];
    const float* mW0 = (const float*)d_in[11];
    const float* mb0 = (const float*)d_in[12];
    const float* mW1 = (const float*)d_in[13];
    const float* mb1 = (const float*)d_in[14];

    const int B = in_sizes[0] / (3 * NPTS);
    float* out = (float*)d_out;

    void *p_idx, *p_feat, *p_pth, *p_ptl, *p_g0h, *p_g0l, *p_gfh, *p_gfl;
    void *p_m0h, *p_m0l, *p_msf, *p_part, *p_wh, *p_wl;
    cudaGetSymbolAddress(&p_idx,  g_idx);
    cudaGetSymbolAddress(&p_feat, g_feat);
    cudaGetSymbolAddress(&p_pth,  g_pt_h);   cudaGetSymbolAddress(&p_ptl,  g_pt_l);
    cudaGetSymbolAddress(&p_g0h,  g_gf0_h);  cudaGetSymbolAddress(&p_g0l,  g_gf0_l);
    cudaGetSymbolAddress(&p_gfh,  g_gf_h);   cudaGetSymbolAddress(&p_gfl,  g_gf_l);
    cudaGetSymbolAddress(&p_m0h,  g_msf0_h); cudaGetSymbolAddress(&p_m0l,  g_msf0_l);
    cudaGetSymbolAddress(&p_msf,  g_msf_t);
    cudaGetSymbolAddress(&p_part, g_part);
    cudaGetSymbolAddress(&p_wh,   g_w_h);    cudaGetSymbolAddress(&p_wl,   g_w_l);

    __nv_bfloat16* wh = (__nv_bfloat16*)p_wh;
    __nv_bfloat16* wl = (__nv_bfloat16*)p_wl;
    const int OFF_G0 = 0, OFF_G1 = 98304, OFF_M0 = 360448, OFF_M1 = 622592;

    cudaFuncSetAttribute(feat_kernel,
                         cudaFuncAttributeMaxDynamicSharedMemorySize, SMEM_FEAT_BYTES);
    cudaFuncSetAttribute(gemm_mma,
                         cudaFuncAttributeMaxDynamicSharedMemorySize, SMEM_GEMM_BYTES);

    // 0) split weights to bf16 hi/lo
    split_kernel<<<98304 / 1024, 256>>>(gW0, wh + OFF_G0, wl + OFF_G0, 98304);
    split_kernel<<<262144 / 1024, 256>>>(gW1, wh + OFF_G1, wl + OFF_G1, 262144);
    split_kernel<<<262144 / 1024, 256>>>(mW0, wh + OFF_M0, wl + OFF_M0, 262144);
    split_kernel<<<32768 / 1024, 256>>>(mW1, wh + OFF_M1, wl + OFF_M1, 32768);

    // 1) KNN
    knn_kernel<<<dim3(NPTS / 8, B), 256>>>(x, (int*)p_idx);

    // 2) per-point MLP features
    feat_kernel<<<dim3(NPTS / 128, 3, B), 128, SMEM_FEAT_BYTES>>>(
        x, sW0, sb0, sW1, sb1, sW2, sb2, (float*)p_feat, B);

    // 3) gather-max -> point planes
    maxpool_kernel<<<dim3(NPTS / 8, 3, B), 256>>>(
        (const float*)p_feat, (const int*)p_idx,
        (__nv_bfloat16*)p_pth, (__nv_bfloat16*)p_ptl, B);

    // 4) gf0 = relu(gW0 @ point)   M=256,K=384
    gemm_mma<<<dim3(2, NPTS / 128, B), 256, SMEM_GEMM_BYTES>>>(
        wh + OFF_G0, wl + OFF_G0, gb0,
        (const __nv_bfloat16*)p_pth, (const __nv_bfloat16*)p_ptl,
        (__nv_bfloat16*)p_g0h, (__nv_bfloat16*)p_g0l, nullptr, 256, 384);

    // 5) gf = relu(gW1 @ gf0)      M=1024,K=256
    gemm_mma<<<dim3(8, NPTS / 128, B), 256, SMEM_GEMM_BYTES>>>(
        wh + OFF_G1, wl + OFF_G1, gb1,
        (const __nv_bfloat16*)p_g0h, (const __nv_bfloat16*)p_g0l,
        (__nv_bfloat16*)p_gfh, (__nv_bfloat16*)p_gfl, nullptr, 1024, 256);

    // 6) global_feature -> d_out[0 : B*1024]
    rowmax_part<<<dim3(4, 16, B), 256>>>(
        (const __nv_bfloat16*)p_gfh, (const __nv_bfloat16*)p_gfl, (float*)p_part);
    rowmax_fin<<<dim3(4, B), 256>>>((const float*)p_part, out);

    // 7) msf0 = relu(mW0 @ gf)     M=256,K=1024
    gemm_mma<<<dim3(2, NPTS / 128, B), 256, SMEM_GEMM_BYTES>>>(
        wh + OFF_M0, wl + OFF_M0, mb0,
        (const __nv_bfloat16*)p_gfh, (const __nv_bfloat16*)p_gfl,
        (__nv_bfloat16*)p_m0h, (__nv_bfloat16*)p_m0l, nullptr, 256, 1024);

    // 8) msf = relu(mW1 @ msf0)    M=128,K=256 (fp32 out only)
    gemm_mma<<<dim3(1, NPTS / 128, B), 256, SMEM_GEMM_BYTES>>>(
        wh + OFF_M1, wl + OFF_M1, mb1,
        (const __nv_bfloat16*)p_m0h, (const __nv_bfloat16*)p_m0l,
        nullptr, nullptr, (float*)p_msf, 128, 256);

    // 9) transpose -> d_out[B*1024 : ] as [B,128,N]
    transpose_msf<<<dim3(NPTS / 32, 128 / 32, B), dim3(32, 8)>>>(
        (const float*)p_msf, out + (size_t)B * 1024);
}

// round 13
// speedup vs baseline: 1.0497x; 1.0497x over previous
#include <cuda_runtime.h>
#include <cuda_bf16.h>
#include <cuda_fp16.h>
#include <cstdint>

#define NPTS 4096
#define KNB  32
#define BMAX 4

typedef unsigned long long ull;

// ---------------- f32x2 helpers (feat kernel) ----------------
__device__ __forceinline__ ull pack2(float lo, float hi) {
    ull r; asm("mov.b64 %0, {%1, %2};" : "=l"(r) : "f"(lo), "f"(hi)); return r;
}
__device__ __forceinline__ ull ffma2(ull a, ull b, ull c) {
    ull d; asm("fma.rn.f32x2 %0, %1, %2, %3;" : "=l"(d) : "l"(a), "l"(b), "l"(c));
    return d;
}
__device__ __forceinline__ float2 unpack2(ull v) {
    float lo, hi; asm("mov.b64 {%0, %1}, %2;" : "=f"(lo), "=f"(hi) : "l"(v));
    return make_float2(lo, hi);
}

// ---------------- fp16 split + mma helpers ----------------
// 4 fp32 -> 2 packed f16x2 hi + 2 lo (hi+lo carries ~22 mantissa bits)
__device__ __forceinline__ void cvt_split4h(const float* v, uint32_t* h, uint32_t* l) {
#pragma unroll
    for (int j = 0; j < 2; j++) {
        uint32_t hh;
        asm("cvt.rn.f16x2.f32 %0, %1, %2;" : "=r"(hh) : "f"(v[2 * j + 1]), "f"(v[2 * j]));
        const __half2 hv = *(const __half2*)&hh;
        const float f0 = __low2float(hv), f1 = __high2float(hv);
        uint32_t ll;
        asm("cvt.rn.f16x2.f32 %0, %1, %2;" : "=r"(ll)
            : "f"(v[2 * j + 1] - f1), "f"(v[2 * j] - f0));
        h[j] = hh; l[j] = ll;
    }
}
__device__ __forceinline__ void mma_f16(float* c, const uint32_t* a, const uint32_t* b) {
    asm volatile(
        "mma.sync.aligned.m16n8k16.row.col.f32.f16.f16.f32 "
        "{%0,%1,%2,%3}, {%4,%5,%6,%7}, {%8,%9}, {%0,%1,%2,%3};"
        : "+f"(c[0]), "+f"(c[1]), "+f"(c[2]), "+f"(c[3])
        : "r"(a[0]), "r"(a[1]), "r"(a[2]), "r"(a[3]), "r"(b[0]), "r"(b[1]));
}
__device__ __forceinline__ void ldsm4(uint32_t& r0, uint32_t& r1, uint32_t& r2, uint32_t& r3,
                                      uint32_t addr) {
    asm volatile("ldmatrix.sync.aligned.m8n8.x4.shared.b16 {%0,%1,%2,%3}, [%4];"
                 : "=r"(r0), "=r"(r1), "=r"(r2), "=r"(r3) : "r"(addr));
}
__device__ __forceinline__ uint32_t smem_u32(const void* p) {
    uint32_t a;
    asm("{ .reg .u64 t; cvta.to.shared.u64 t, %1; cvt.u32.u64 %0, t; }" : "=r"(a) : "l"(p));
    return a;
}
__device__ __forceinline__ void cp16(uint32_t dst, const void* src) {
    asm volatile("cp.async.ca.shared.global [%0], [%1], 16;" :: "r"(dst), "l"(src));
}

// ---------------- scratch ----------------
__device__ __align__(16) int    g_idx    [BMAX * NPTS * KNB];
__device__ __align__(16) __half g_feat   [(size_t)3 * BMAX * NPTS * 128];   // fp16 plane
__device__ __align__(16) __half g_pt     [(size_t)BMAX * NPTS * 384];       // fp16 exact
__device__ __align__(16) __half g_gf0_h  [(size_t)BMAX * NPTS * 256];
__device__ __align__(16) __half g_gf0_l  [(size_t)BMAX * NPTS * 256];
__device__ __align__(16) __half g_gf_h   [(size_t)BMAX * NPTS * 1024];
__device__ __align__(16) __half g_gf_l   [(size_t)BMAX * NPTS * 1024];
__device__ __align__(16) __half g_msf0_h [(size_t)BMAX * NPTS * 256];
__device__ __align__(16) __half g_msf0_l [(size_t)BMAX * NPTS * 256];
__device__ __align__(16) float  g_msf_t  [(size_t)BMAX * NPTS * 128];
__device__ __align__(16) float  g_part   [BMAX * 16 * 1024];
// weights: gW0(98304) | gW1(262144) | mW0(262144) | mW1(32768)
__device__ __align__(16) __half g_w_h    [655360];
__device__ __align__(16) __half g_w_l    [655360];

#define OFF_G0 0
#define OFF_G1 98304
#define OFF_M0 360448
#define OFF_M1 622592

// =================================================================
// K0: split all 4 weight matrices fp32 -> fp16 hi/lo, one launch
// blocks: [0,96) gW0  [96,352) gW1  [352,608) mW0  [608,640) mW1
// =================================================================
__global__ __launch_bounds__(256) void split_all(
    const float* __restrict__ g0, const float* __restrict__ g1,
    const float* __restrict__ m0, const float* __restrict__ m1,
    __half* __restrict__ wh, __half* __restrict__ wl)
{
    int blk = blockIdx.x;
    const float* src; int base;
    if (blk < 96)       { src = g0; base = OFF_G0; }
    else if (blk < 352) { src = g1; base = OFF_G1; blk -= 96; }
    else if (blk < 608) { src = m0; base = OFF_M0; blk -= 352; }
    else                { src = m1; base = OFF_M1; blk -= 608; }
    const int i = (blk * 256 + threadIdx.x) * 4;
    const float4 v = *(const float4*)(src + i);
    uint32_t hh[2], ll[2];
    cvt_split4h(&v.x, hh, ll);
    *(uint2*)(wh + base + i) = make_uint2(hh[0], hh[1]);
    *(uint2*)(wl + base + i) = make_uint2(ll[0], ll[1]);
}

// =================================================================
// K1: KNN — warp per query, lane-distributed sorted top-32 list
// =================================================================
__global__ __launch_bounds__(256) void knn_kernel(const float* __restrict__ x,
                                                  int* __restrict__ idx)
{
    __shared__ float4 tile[1024];
    const int b = blockIdx.y;
    const int tid = threadIdx.x;
    const int w = tid >> 5, lane = tid & 31;
    const int q = blockIdx.x * 8 + w;
    const float* xb = x + (size_t)b * 3 * NPTS;

    const float qx = xb[q], qy = xb[NPTS + q], qz = xb[2 * NPTS + q];
    const float qsq = qx * qx + qy * qy + qz * qz;

    float v = 3.0e38f;
    int   vi = 0x7fffffff;
    float cm = 3.0e38f;

    for (int t0 = 0; t0 < NPTS; t0 += 1024) {
        __syncthreads();
        for (int i = tid; i < 1024; i += 256) {
            const int g = t0 + i;
            const float cx = xb[g], cy = xb[NPTS + g], cz = xb[2 * NPTS + g];
            tile[i] = make_float4(cx, cy, cz, cx * cx + cy * cy + cz * cz);
        }
        __syncthreads();

        for (int c = 0; c < 32; c++) {
            const int gbase = t0 + c * 32;
            const float4 p = tile[c * 32 + lane];
            float d = qsq + p.w - 2.0f * fmaf(qx, p.x, fmaf(qy, p.y, qz * p.z));
            if (gbase + lane == q) d = 3.0e38f;

            unsigned m = __ballot_sync(0xffffffffu, d < cm);
            while (m) {
                const int src = __ffs(m) - 1; m &= m - 1;
                const float dd = __shfl_sync(0xffffffffu, d, src);
                const int   ii = gbase + src;
                const unsigned less = __ballot_sync(0xffffffffu,
                        (v < dd) || (v == dd && vi < ii));
                const int pos = __popc(less);
                const float pv = __shfl_up_sync(0xffffffffu, v, 1);
                const int   pi = __shfl_up_sync(0xffffffffu, vi, 1);
                if (pos < 32) {
                    if (lane == pos)      { v = dd; vi = ii; }
                    else if (lane > pos)  { v = pv; vi = pi; }
                }
                cm = __shfl_sync(0xffffffffu, v, 31);
            }
        }
    }
    idx[((size_t)b * NPTS + q) * KNB + lane] = vi;
}

// =================================================================
// K2: per-point 3-layer MLP (3->64->64->128), f32x2 math, fp16 out
// =================================================================
#define SMEM_FEAT_FLOATS (192 + 64 + 4096 + 64 + 8192 + 128)
#define SMEM_FEAT_BYTES  (SMEM_FEAT_FLOATS * 4)

__global__ __launch_bounds__(128) void feat_kernel(
    const float* __restrict__ x,
    const float* __restrict__ sW0, const float* __restrict__ sb0,
    const float* __restrict__ sW1, const float* __restrict__ sb1,
    const float* __restrict__ sW2, const float* __restrict__ sb2,
    __half* __restrict__ feat, int B)
{
    extern __shared__ float sm[];
    float* w0s = sm;
    float* b0s = w0s + 192;
    float* w1s = b0s + 64;
    float* b1s = w1s + 4096;
    float* w2s = b1s + 64;
    float* b2s = w2s + 8192;

    const int s = blockIdx.y, b = blockIdx.z;
    const int tid = threadIdx.x;

    for (int i = tid; i < 192;  i += 128) w0s[i] = sW0[s * 192 + i];
    for (int i = tid; i < 64;   i += 128) { b0s[i] = sb0[s * 64 + i]; b1s[i] = sb1[s * 64 + i]; }
    for (int i = tid; i < 4096; i += 128) w1s[i] = sW1[s * 4096 + i];
    for (int i = tid; i < 8192; i += 128) w2s[i] = sW2[s * 8192 + i];
    for (int i = tid; i < 128;  i += 128) b2s[i] = sb2[s * 128 + i];
    __syncthreads();

    const int j = blockIdx.x * 128 + tid;
    const float* xb = x + (size_t)b * 3 * NPTS;
    const float px = xb[j], py = xb[NPTS + j], pz = xb[2 * NPTS + j];

    float h0[64];
#pragma unroll
    for (int o = 0; o < 64; o++) {
        float a = fmaf(w0s[o * 3 + 2], pz,
                  fmaf(w0s[o * 3 + 1], py,
                  fmaf(w0s[o * 3 + 0], px, b0s[o])));
        h0[o] = fmaxf(a, 0.0f);
    }

    ull hp[32];
#pragma unroll
    for (int c = 0; c < 32; c++) hp[c] = pack2(h0[2 * c], h0[2 * c + 1]);

    float h1[64];
#pragma unroll
    for (int o = 0; o < 64; o += 2) {
        ull a0 = 0ull, a1 = 0ull;
        const ull* r0 = (const ull*)(w1s + (o    ) * 64);
        const ull* r1 = (const ull*)(w1s + (o + 1) * 64);
#pragma unroll
        for (int c = 0; c < 32; c++) {
            a0 = ffma2(r0[c], hp[c], a0);
            a1 = ffma2(r1[c], hp[c], a1);
        }
        const float2 u0 = unpack2(a0), u1 = unpack2(a1);
        h1[o]     = fmaxf(u0.x + u0.y + b1s[o],     0.0f);
        h1[o + 1] = fmaxf(u1.x + u1.y + b1s[o + 1], 0.0f);
    }

#pragma unroll
    for (int c = 0; c < 32; c++) hp[c] = pack2(h1[2 * c], h1[2 * c + 1]);

    __half* fout = feat + ((size_t)(s * B + b) * NPTS + j) * 128;
    for (int o = 0; o < 128; o += 4) {
        ull a0 = 0ull, a1 = 0ull, a2 = 0ull, a3 = 0ull;
        const ull* r0 = (const ull*)(w2s + (size_t)(o    ) * 64);
        const ull* r1 = (const ull*)(w2s + (size_t)(o + 1) * 64);
        const ull* r2 = (const ull*)(w2s + (size_t)(o + 2) * 64);
        const ull* r3 = (const ull*)(w2s + (size_t)(o + 3) * 64);
#pragma unroll
        for (int c = 0; c < 32; c++) {
            a0 = ffma2(r0[c], hp[c], a0);
            a1 = ffma2(r1[c], hp[c], a1);
            a2 = ffma2(r2[c], hp[c], a2);
            a3 = ffma2(r3[c], hp[c], a3);
        }
        const float2 u0 = unpack2(a0), u1 = unpack2(a1);
        const float2 u2 = unpack2(a2), u3 = unpack2(a3);
        const float v0 = fmaxf(u0.x + u0.y + b2s[o],     0.0f);
        const float v1 = fmaxf(u1.x + u1.y + b2s[o + 1], 0.0f);
        const float v2 = fmaxf(u2.x + u2.y + b2s[o + 2], 0.0f);
        const float v3 = fmaxf(u3.x + u3.y + b2s[o + 3], 0.0f);
        uint32_t p0, p1;
        asm("cvt.rn.f16x2.f32 %0, %1, %2;" : "=r"(p0) : "f"(v1), "f"(v0));
        asm("cvt.rn.f16x2.f32 %0, %1, %2;" : "=r"(p1) : "f"(v3), "f"(v2));
        *(uint2*)(fout + o) = make_uint2(p0, p1);
    }
}

// =================================================================
// K3: gather-max over 32 neighbors (fp16, exact) -> pt[b][n][384]
// =================================================================
__global__ __launch_bounds__(256) void maxpool_kernel(
    const __half* __restrict__ feat, const int* __restrict__ idx,
    __half* __restrict__ pt, int B)
{
    const int s = blockIdx.y, b = blockIdx.z;
    const int tid = threadIdx.x;
    const int w = tid >> 5, lane = tid & 31;
    const int n = blockIdx.x * 8 + w;

    const int ki = idx[((size_t)b * NPTS + n) * KNB + lane];
    const __half* fb = feat + (size_t)(s * B + b) * NPTS * 128;

    __half2 m01 = __float2half2_rn(0.0f);   // relu => feat >= 0
    __half2 m23 = __float2half2_rn(0.0f);
#pragma unroll
    for (int k = 0; k < KNB; k++) {
        const int j = __shfl_sync(0xffffffffu, ki, k);
        const uint2 vv = *(const uint2*)(fb + (size_t)j * 128 + lane * 4);
        m01 = __hmax2(m01, *(const __half2*)&vv.x);
        m23 = __hmax2(m23, *(const __half2*)&vv.y);
    }
    const size_t ofs = ((size_t)b * NPTS + n) * 384 + s * 128 + lane * 4;
    *(uint2*)(pt + ofs) = make_uint2(*(const uint32_t*)&m01, *(const uint32_t*)&m23);
}

// =================================================================
// K4: mma.sync fp16 GEMM on pre-split hi/lo planes, cp.async loads.
// Xl == nullptr => B is a single exact fp16 plane (2 products).
// CTA 128x128, 8 warps (2M x 4N), k-chunk 32, 2-stage pipeline.
// =================================================================
#define KCH    32
#define PITCH  80
#define TILEB  (128 * PITCH)
#define STG_B  (4 * TILEB)
#define SMEM_GEMM_BYTES (2 * STG_B)      // 81920

__global__ __launch_bounds__(256, 2) void gemm_mma(
    const __half* __restrict__ Wh, const __half* __restrict__ Wl,
    const float* __restrict__ bias,
    const __half* __restrict__ Xh, const __half* __restrict__ Xl,
    __half* __restrict__ Yh, __half* __restrict__ Yl,
    float* __restrict__ Yf, int M, int K)
{
    extern __shared__ __align__(16) char smem[];
    const uint32_t sb = smem_u32(smem);

    const int tid = threadIdx.x, wid = tid >> 5, lane = tid & 31;
    const int wm = wid & 1, wn = wid >> 1;
    const int m0 = blockIdx.x * 128, n0 = blockIdx.y * 128;
    const int bi = blockIdx.z;
    const size_t xrow0 = (size_t)bi * NPTS + n0;
    const bool dual = (Xl != nullptr);

    const uint32_t aOff = (uint32_t)(wm * 64 + (lane & 7) + ((lane >> 3) & 1) * 8) * PITCH
                        + ((lane >> 4) & 1) * 16;
    const uint32_t bOff = (uint32_t)(wn * 32 + (lane & 7) + ((lane >> 4) & 1) * 8) * PITCH
                        + ((lane >> 3) & 1) * 16;

    float acc[4][4][4];
#pragma unroll
    for (int i = 0; i < 4; i++)
#pragma unroll
        for (int j = 0; j < 4; j++)
#pragma unroll
            for (int r = 0; r < 4; r++) acc[i][j][r] = 0.0f;

    const int nch = K / KCH;

    auto issue = [&](int ch, int stg) {
        const uint32_t sbase = sb + (uint32_t)stg * STG_B;
        const int kof = ch * KCH;
#pragma unroll
        for (int r = 0; r < 2; r++) {
            const int unit = tid + r * 256;
            const int row = unit >> 2, seg = unit & 3;
            const uint32_t d = sbase + (uint32_t)row * PITCH + seg * 16;
            const size_t aidx = (size_t)(m0 + row) * K + kof + seg * 8;
            const size_t bidx = (xrow0 + row) * K + kof + seg * 8;
            cp16(d,             Wh + aidx);
            cp16(d + TILEB,     Wl + aidx);
            cp16(d + 2 * TILEB, Xh + bidx);
            if (dual) cp16(d + 3 * TILEB, Xl + bidx);
        }
        asm volatile("cp.async.commit_group;" ::: "memory");
    };

    issue(0, 0);

    for (int ch = 0; ch < nch; ch++) {
        const int cur = ch & 1;
        const bool more = (ch + 1 < nch);
        if (more) issue(ch + 1, cur ^ 1);
        if (more) asm volatile("cp.async.wait_group 1;" ::: "memory");
        else      asm volatile("cp.async.wait_group 0;" ::: "memory");
        __syncthreads();

        const uint32_t aT = sb + (uint32_t)cur * STG_B + aOff;
        const uint32_t bT = sb + (uint32_t)cur * STG_B + 2 * TILEB + bOff;
#pragma unroll
        for (int ks = 0; ks < 2; ks++) {
            const uint32_t kso = ks * 32;
            uint32_t bh[4][2], bl[4][2];
            ldsm4(bh[0][0], bh[0][1], bh[1][0], bh[1][1], bT + kso);
            ldsm4(bh[2][0], bh[2][1], bh[3][0], bh[3][1], bT + 16 * PITCH + kso);
            if (dual) {
                ldsm4(bl[0][0], bl[0][1], bl[1][0], bl[1][1], bT + TILEB + kso);
                ldsm4(bl[2][0], bl[2][1], bl[3][0], bl[3][1], bT + TILEB + 16 * PITCH + kso);
            }
#pragma unroll
            for (int mih = 0; mih < 2; mih++) {
                uint32_t ah[2][4], al[2][4];
#pragma unroll
                for (int mi2 = 0; mi2 < 2; mi2++) {
                    const uint32_t ao = aT + (uint32_t)(mih * 2 + mi2) * (16 * PITCH) + kso;
                    ldsm4(ah[mi2][0], ah[mi2][1], ah[mi2][2], ah[mi2][3], ao);
                    ldsm4(al[mi2][0], al[mi2][1], al[mi2][2], al[mi2][3], ao + TILEB);
                }
#pragma unroll
                for (int mi2 = 0; mi2 < 2; mi2++)
#pragma unroll
                    for (int ni = 0; ni < 4; ni++) {
                        float* c = acc[mih * 2 + mi2][ni];
                        mma_f16(c, ah[mi2], bh[ni]);
                        mma_f16(c, al[mi2], bh[ni]);
                        if (dual) mma_f16(c, ah[mi2], bl[ni]);
                    }
            }
        }
        __syncthreads();
    }

    // epilogue
    const int g = lane >> 2, t2 = (lane & 3) * 2;
#pragma unroll
    for (int mi = 0; mi < 4; mi++) {
        const int mlo = m0 + wm * 64 + mi * 16 + g;
        const float bv0 = bias[mlo], bv1 = bias[mlo + 8];
#pragma unroll
        for (int ni = 0; ni < 4; ni++) {
            const int n = n0 + wn * 32 + ni * 8 + t2;
            const size_t r0 = ((size_t)bi * NPTS + n) * M;
            const size_t r1 = r0 + M;
            float vv[4];
            vv[0] = fmaxf(acc[mi][ni][0] + bv0, 0.0f);
            vv[1] = fmaxf(acc[mi][ni][1] + bv0, 0.0f);
            vv[2] = fmaxf(acc[mi][ni][2] + bv1, 0.0f);
            vv[3] = fmaxf(acc[mi][ni][3] + bv1, 0.0f);
            if (Yh) {
#pragma unroll
                for (int q = 0; q < 4; q++) {
                    const size_t o = (q & 1 ? r1 : r0) + mlo + (q >> 1) * 8;
                    const __half hb = __float2half_rn(vv[q]);
                    Yh[o] = hb;
                    Yl[o] = __float2half_rn(vv[q] - __half2float(hb));
                }
            }
            if (Yf) {
                Yf[r0 + mlo]     = vv[0];
                Yf[r1 + mlo]     = vv[1];
                Yf[r0 + mlo + 8] = vv[2];
                Yf[r1 + mlo + 8] = vv[3];
            }
        }
    }
}

// =================================================================
// rowmax on gf planes (hi+lo), two-phase
// =================================================================
__global__ __launch_bounds__(256) void rowmax_part(const __half* __restrict__ gh,
                                                   const __half* __restrict__ gl,
                                                   float* __restrict__ part)
{
    const int c = blockIdx.x * 256 + threadIdx.x;
    const int ns = blockIdx.y, b = blockIdx.z;
    const size_t base = ((size_t)b * NPTS + ns * 256) * 1024 + c;
    float m0 = -3.0e38f, m1 = -3.0e38f, m2 = -3.0e38f, m3 = -3.0e38f;
#pragma unroll 4
    for (int n = 0; n < 256; n += 4) {
        m0 = fmaxf(m0, __half2float(gh[base + (size_t)(n    ) * 1024]) +
                       __half2float(gl[base + (size_t)(n    ) * 1024]));
        m1 = fmaxf(m1, __half2float(gh[base + (size_t)(n + 1) * 1024]) +
                       __half2float(gl[base + (size_t)(n + 1) * 1024]));
        m2 = fmaxf(m2, __half2float(gh[base + (size_t)(n + 2) * 1024]) +
                       __half2float(gl[base + (size_t)(n + 2) * 1024]));
        m3 = fmaxf(m3, __half2float(gh[base + (size_t)(n + 3) * 1024]) +
                       __half2float(gl[base + (size_t)(n + 3) * 1024]));
    }
    part[(size_t)(b * 16 + ns) * 1024 + c] = fmaxf(fmaxf(m0, m1), fmaxf(m2, m3));
}

__global__ __launch_bounds__(256) void rowmax_fin(const float* __restrict__ part,
                                                  float* __restrict__ out)
{
    const int c = blockIdx.x * 256 + threadIdx.x;
    const int b = blockIdx.y;
    float m = -3.0e38f;
#pragma unroll
    for (int i = 0; i < 16; i++)
        m = fmaxf(m, part[(size_t)(b * 16 + i) * 1024 + c]);
    out[(size_t)b * 1024 + c] = m;
}

// =================================================================
// transpose msf_t[b][n][128] -> out[b][128][n]
// =================================================================
__global__ void transpose_msf(const float* __restrict__ in, float* __restrict__ out)
{
    __shared__ float t[32][33];
    const int b = blockIdx.z;
    const int n0 = blockIdx.x * 32, c0 = blockIdx.y * 32;
    const int tx = threadIdx.x, ty = threadIdx.y;
#pragma unroll
    for (int r = 0; r < 32; r += 8)
        t[ty + r][tx] = in[(size_t)((size_t)b * NPTS + n0 + ty + r) * 128 + c0 + tx];
    __syncthreads();
#pragma unroll
    for (int r = 0; r < 32; r += 8)
        out[(size_t)((size_t)b * 128 + c0 + ty + r) * NPTS + n0 + tx] = t[tx][ty + r];
}

// =================================================================
extern "C" void kernel_launch(void* const* d_in, const int* in_sizes, int n_in,
                              void* d_out, int out_size)
{
    const float* x   = (const float*)d_in[0];
    const float* sW0 = (const float*)d_in[1];
    const float* sb0 = (const float*)d_in[2];
    const float* sW1 = (const float*)d_in[3];
    const float* sb1 = (const float*)d_in[4];
    const float* sW2 = (const float*)d_in[5];
    const float* sb2 = (const float*)d_in[6];
    const float* gW0 = (const float*)d_in[7];
    const float* gb0 = (const float*)d_in[8];
    const float* gW1 = (const float*)d_in[9];
    const float* gb1 = (const float*)d_in[10];
    const float* mW0 = (const float*)d_in[11];
    const float* mb0 = (const float*)d_in[12];
    const float* mW1 = (const float*)d_in[13];
    const float* mb1 = (const float*)d_in[14];

    const int B = in_sizes[0] / (3 * NPTS);
    float* out = (float*)d_out;

    void *p_idx, *p_feat, *p_pt, *p_g0h, *p_g0l, *p_gfh, *p_gfl;
    void *p_m0h, *p_m0l, *p_msf, *p_part, *p_wh, *p_wl;
    cudaGetSymbolAddress(&p_idx,  g_idx);
    cudaGetSymbolAddress(&p_feat, g_feat);
    cudaGetSymbolAddress(&p_pt,   g_pt);
    cudaGetSymbolAddress(&p_g0h,  g_gf0_h);  cudaGetSymbolAddress(&p_g0l,  g_gf0_l);
    cudaGetSymbolAddress(&p_gfh,  g_gf_h);   cudaGetSymbolAddress(&p_gfl,  g_gf_l);
    cudaGetSymbolAddress(&p_m0h,  g_msf0_h); cudaGetSymbolAddress(&p_m0l,  g_msf0_l);
    cudaGetSymbolAddress(&p_msf,  g_msf_t);
    cudaGetSymbolAddress(&p_part, g_part);
    cudaGetSymbolAddress(&p_wh,   g_w_h);    cudaGetSymbolAddress(&p_wl,   g_w_l);

    __half* wh = (__half*)p_wh;
    __half* wl = (__half*)p_wl;

    cudaFuncSetAttribute(feat_kernel,
                         cudaFuncAttributeMaxDynamicSharedMemorySize, SMEM_FEAT_BYTES);
    cudaFuncSetAttribute(gemm_mma,
                         cudaFuncAttributeMaxDynamicSharedMemorySize, SMEM_GEMM_BYTES);

    // 0) split weights (single launch)
    split_all<<<640, 256>>>(gW0, gW1, mW0, mW1, wh, wl);

    // 1) KNN
    knn_kernel<<<dim3(NPTS / 8, B), 256>>>(x, (int*)p_idx);

    // 2) per-point MLP features (fp16 plane)
    feat_kernel<<<dim3(NPTS / 128, 3, B), 128, SMEM_FEAT_BYTES>>>(
        x, sW0, sb0, sW1, sb1, sW2, sb2, (__half*)p_feat, B);

    // 3) gather-max -> pt[b][n][384] (fp16, exact max)
    maxpool_kernel<<<dim3(NPTS / 8, 3, B), 256>>>(
        (const __half*)p_feat, (const int*)p_idx, (__half*)p_pt, B);

    // 4) gf0 = relu(gW0 @ point)   M=256,K=384  (B single plane)
    gemm_mma<<<dim3(2, NPTS / 128, B), 256, SMEM_GEMM_BYTES>>>(
        wh + OFF_G0, wl + OFF_G0, gb0,
        (const __half*)p_pt, nullptr,
        (__half*)p_g0h, (__half*)p_g0l, nullptr, 256, 384);

    // 5) gf = relu(gW1 @ gf0)      M=1024,K=256
    gemm_mma<<<dim3(8, NPTS / 128, B), 256, SMEM_GEMM_BYTES>>>(
        wh + OFF_G1, wl + OFF_G1, gb1,
        (const __half*)p_g0h, (const __half*)p_g0l,
        (__half*)p_gfh, (__half*)p_gfl, nullptr, 1024, 256);

    // 6) global_feature -> d_out[0 : B*1024]
    rowmax_part<<<dim3(4, 16, B), 256>>>(
        (const __half*)p_gfh, (const __half*)p_gfl, (float*)p_part);
    rowmax_fin<<<dim3(4, B), 256>>>((const float*)p_part, out);

    // 7) msf0 = relu(mW0 @ gf)     M=256,K=1024
    gemm_mma<<<dim3(2, NPTS / 128, B), 256, SMEM_GEMM_BYTES>>>(
        wh + OFF_M0, wl + OFF_M0, mb0,
        (const __half*)p_gfh, (const __half*)p_gfl,
        (__half*)p_m0h, (__half*)p_m0l, nullptr, 256, 1024);

    // 8) msf = relu(mW1 @ msf0)    M=128,K=256 (fp32 out)
    gemm_mma<<<dim3(1, NPTS / 128, B), 256, SMEM_GEMM_BYTES>>>(
        wh + OFF_M1, wl + OFF_M1, mb1,
        (const __half*)p_m0h, (const __half*)p_m0l,
        nullptr, nullptr, (float*)p_msf, 128, 256);

    // 9) transpose -> d_out[B*1024 : ] as [B,128,N]
    transpose_msf<<<dim3(NPTS / 32, 128 / 32, B), dim3(32, 8)>>>(
        (const float*)p_msf, out + (size_t)B * 1024);
}

// round 14
// speedup vs baseline: 1.0904x; 1.0388x over previous
#include <cuda_runtime.h>
#include <cuda_bf16.h>
#include <cuda_fp16.h>
#include <cstdint>

#define NPTS 4096
#define KNB  32
#define BMAX 4

typedef unsigned long long ull;

// ---------------- f32x2 helpers (feat kernel) ----------------
__device__ __forceinline__ ull pack2(float lo, float hi) {
    ull r; asm("mov.b64 %0, {%1, %2};" : "=l"(r) : "f"(lo), "f"(hi)); return r;
}
__device__ __forceinline__ ull ffma2(ull a, ull b, ull c) {
    ull d; asm("fma.rn.f32x2 %0, %1, %2, %3;" : "=l"(d) : "l"(a), "l"(b), "l"(c));
    return d;
}
__device__ __forceinline__ float2 unpack2(ull v) {
    float lo, hi; asm("mov.b64 {%0, %1}, %2;" : "=f"(lo), "=f"(hi) : "l"(v));
    return make_float2(lo, hi);
}

// ---------------- fp16 split + mma helpers ----------------
__device__ __forceinline__ void cvt_split4h(const float* v, uint32_t* h, uint32_t* l) {
#pragma unroll
    for (int j = 0; j < 2; j++) {
        uint32_t hh;
        asm("cvt.rn.f16x2.f32 %0, %1, %2;" : "=r"(hh) : "f"(v[2 * j + 1]), "f"(v[2 * j]));
        const __half2 hv = *(const __half2*)&hh;
        const float f0 = __low2float(hv), f1 = __high2float(hv);
        uint32_t ll;
        asm("cvt.rn.f16x2.f32 %0, %1, %2;" : "=r"(ll)
            : "f"(v[2 * j + 1] - f1), "f"(v[2 * j] - f0));
        h[j] = hh; l[j] = ll;
    }
}
__device__ __forceinline__ void mma_f16(float* c, const uint32_t* a, const uint32_t* b) {
    asm volatile(
        "mma.sync.aligned.m16n8k16.row.col.f32.f16.f16.f32 "
        "{%0,%1,%2,%3}, {%4,%5,%6,%7}, {%8,%9}, {%0,%1,%2,%3};"
        : "+f"(c[0]), "+f"(c[1]), "+f"(c[2]), "+f"(c[3])
        : "r"(a[0]), "r"(a[1]), "r"(a[2]), "r"(a[3]), "r"(b[0]), "r"(b[1]));
}
__device__ __forceinline__ void ldsm4(uint32_t& r0, uint32_t& r1, uint32_t& r2, uint32_t& r3,
                                      uint32_t addr) {
    asm volatile("ldmatrix.sync.aligned.m8n8.x4.shared.b16 {%0,%1,%2,%3}, [%4];"
                 : "=r"(r0), "=r"(r1), "=r"(r2), "=r"(r3) : "r"(addr));
}
__device__ __forceinline__ uint32_t smem_u32(const void* p) {
    uint32_t a;
    asm("{ .reg .u64 t; cvta.to.shared.u64 t, %1; cvt.u32.u64 %0, t; }" : "=r"(a) : "l"(p));
    return a;
}
__device__ __forceinline__ void cp16(uint32_t dst, const void* src) {
    asm volatile("cp.async.ca.shared.global [%0], [%1], 16;" :: "r"(dst), "l"(src));
}

// ---------------- scratch ----------------
__device__ __align__(16) int    g_idx    [BMAX * NPTS * KNB];
__device__ __align__(16) __half g_feat   [(size_t)3 * BMAX * NPTS * 128];
__device__ __align__(16) __half g_pt     [(size_t)BMAX * NPTS * 384];
__device__ __align__(16) __half g_gf0_h  [(size_t)BMAX * NPTS * 256];
__device__ __align__(16) __half g_gf0_l  [(size_t)BMAX * NPTS * 256];
__device__ __align__(16) __half g_gf_h   [(size_t)BMAX * NPTS * 1024];
__device__ __align__(16) __half g_gf_l   [(size_t)BMAX * NPTS * 1024];
__device__ __align__(16) __half g_msf0_h [(size_t)BMAX * NPTS * 256];
__device__ __align__(16) __half g_msf0_l [(size_t)BMAX * NPTS * 256];
__device__ __align__(16) float  g_msf_t  [(size_t)BMAX * NPTS * 128];
__device__ __align__(16) float  g_part   [BMAX * 16 * 1024];
__device__ __align__(16) __half g_w_h    [655360];
__device__ __align__(16) __half g_w_l    [655360];

#define OFF_G0 0
#define OFF_G1 98304
#define OFF_M0 360448
#define OFF_M1 622592

// =================================================================
// K0: split all 4 weight matrices fp32 -> fp16 hi/lo, one launch
// =================================================================
__global__ __launch_bounds__(256) void split_all(
    const float* __restrict__ g0, const float* __restrict__ g1,
    const float* __restrict__ m0, const float* __restrict__ m1,
    __half* __restrict__ wh, __half* __restrict__ wl)
{
    int blk = blockIdx.x;
    const float* src; int base;
    if (blk < 96)       { src = g0; base = OFF_G0; }
    else if (blk < 352) { src = g1; base = OFF_G1; blk -= 96; }
    else if (blk < 608) { src = m0; base = OFF_M0; blk -= 352; }
    else                { src = m1; base = OFF_M1; blk -= 608; }
    const int i = (blk * 256 + threadIdx.x) * 4;
    const float4 v = *(const float4*)(src + i);
    uint32_t hh[2], ll[2];
    cvt_split4h(&v.x, hh, ll);
    *(uint2*)(wh + base + i) = make_uint2(hh[0], hh[1]);
    *(uint2*)(wl + base + i) = make_uint2(ll[0], ll[1]);
}

// =================================================================
// K1: KNN — warp per query, lane-distributed sorted top-32 list
// =================================================================
__global__ __launch_bounds__(256) void knn_kernel(const float* __restrict__ x,
                                                  int* __restrict__ idx)
{
    __shared__ float4 tile[1024];
    const int b = blockIdx.y;
    const int tid = threadIdx.x;
    const int w = tid >> 5, lane = tid & 31;
    const int q = blockIdx.x * 8 + w;
    const float* xb = x + (size_t)b * 3 * NPTS;

    const float qx = xb[q], qy = xb[NPTS + q], qz = xb[2 * NPTS + q];
    const float qsq = qx * qx + qy * qy + qz * qz;

    float v = 3.0e38f;
    int   vi = 0x7fffffff;
    float cm = 3.0e38f;

    for (int t0 = 0; t0 < NPTS; t0 += 1024) {
        __syncthreads();
        for (int i = tid; i < 1024; i += 256) {
            const int g = t0 + i;
            const float cx = xb[g], cy = xb[NPTS + g], cz = xb[2 * NPTS + g];
            tile[i] = make_float4(cx, cy, cz, cx * cx + cy * cy + cz * cz);
        }
        __syncthreads();

        for (int c = 0; c < 32; c++) {
            const int gbase = t0 + c * 32;
            const float4 p = tile[c * 32 + lane];
            float d = qsq + p.w - 2.0f * fmaf(qx, p.x, fmaf(qy, p.y, qz * p.z));
            if (gbase + lane == q) d = 3.0e38f;

            unsigned m = __ballot_sync(0xffffffffu, d < cm);
            while (m) {
                const int src = __ffs(m) - 1; m &= m - 1;
                const float dd = __shfl_sync(0xffffffffu, d, src);
                const int   ii = gbase + src;
                const unsigned less = __ballot_sync(0xffffffffu,
                        (v < dd) || (v == dd && vi < ii));
                const int pos = __popc(less);
                const float pv = __shfl_up_sync(0xffffffffu, v, 1);
                const int   pi = __shfl_up_sync(0xffffffffu, vi, 1);
                if (pos < 32) {
                    if (lane == pos)      { v = dd; vi = ii; }
                    else if (lane > pos)  { v = pv; vi = pi; }
                }
                cm = __shfl_sync(0xffffffffu, v, 31);
            }
        }
    }
    idx[((size_t)b * NPTS + q) * KNB + lane] = vi;
}

// =================================================================
// K2: per-point 3-layer MLP (3->64->64->128), f32x2 math, fp16 out
// =================================================================
#define SMEM_FEAT_FLOATS (192 + 64 + 4096 + 64 + 8192 + 128)
#define SMEM_FEAT_BYTES  (SMEM_FEAT_FLOATS * 4)

__global__ __launch_bounds__(128) void feat_kernel(
    const float* __restrict__ x,
    const float* __restrict__ sW0, const float* __restrict__ sb0,
    const float* __restrict__ sW1, const float* __restrict__ sb1,
    const float* __restrict__ sW2, const float* __restrict__ sb2,
    __half* __restrict__ feat, int B)
{
    extern __shared__ float sm[];
    float* w0s = sm;
    float* b0s = w0s + 192;
    float* w1s = b0s + 64;
    float* b1s = w1s + 4096;
    float* w2s = b1s + 64;
    float* b2s = w2s + 8192;

    const int s = blockIdx.y, b = blockIdx.z;
    const int tid = threadIdx.x;

    for (int i = tid; i < 192;  i += 128) w0s[i] = sW0[s * 192 + i];
    for (int i = tid; i < 64;   i += 128) { b0s[i] = sb0[s * 64 + i]; b1s[i] = sb1[s * 64 + i]; }
    for (int i = tid; i < 4096; i += 128) w1s[i] = sW1[s * 4096 + i];
    for (int i = tid; i < 8192; i += 128) w2s[i] = sW2[s * 8192 + i];
    for (int i = tid; i < 128;  i += 128) b2s[i] = sb2[s * 128 + i];
    __syncthreads();

    const int j = blockIdx.x * 128 + tid;
    const float* xb = x + (size_t)b * 3 * NPTS;
    const float px = xb[j], py = xb[NPTS + j], pz = xb[2 * NPTS + j];

    float h0[64];
#pragma unroll
    for (int o = 0; o < 64; o++) {
        float a = fmaf(w0s[o * 3 + 2], pz,
                  fmaf(w0s[o * 3 + 1], py,
                  fmaf(w0s[o * 3 + 0], px, b0s[o])));
        h0[o] = fmaxf(a, 0.0f);
    }

    ull hp[32];
#pragma unroll
    for (int c = 0; c < 32; c++) hp[c] = pack2(h0[2 * c], h0[2 * c + 1]);

    float h1[64];
#pragma unroll
    for (int o = 0; o < 64; o += 2) {
        ull a0 = 0ull, a1 = 0ull;
        const ull* r0 = (const ull*)(w1s + (o    ) * 64);
        const ull* r1 = (const ull*)(w1s + (o + 1) * 64);
#pragma unroll
        for (int c = 0; c < 32; c++) {
            a0 = ffma2(r0[c], hp[c], a0);
            a1 = ffma2(r1[c], hp[c], a1);
        }
        const float2 u0 = unpack2(a0), u1 = unpack2(a1);
        h1[o]     = fmaxf(u0.x + u0.y + b1s[o],     0.0f);
        h1[o + 1] = fmaxf(u1.x + u1.y + b1s[o + 1], 0.0f);
    }

#pragma unroll
    for (int c = 0; c < 32; c++) hp[c] = pack2(h1[2 * c], h1[2 * c + 1]);

    __half* fout = feat + ((size_t)(s * B + b) * NPTS + j) * 128;
    for (int o = 0; o < 128; o += 4) {
        ull a0 = 0ull, a1 = 0ull, a2 = 0ull, a3 = 0ull;
        const ull* r0 = (const ull*)(w2s + (size_t)(o    ) * 64);
        const ull* r1 = (const ull*)(w2s + (size_t)(o + 1) * 64);
        const ull* r2 = (const ull*)(w2s + (size_t)(o + 2) * 64);
        const ull* r3 = (const ull*)(w2s + (size_t)(o + 3) * 64);
#pragma unroll
        for (int c = 0; c < 32; c++) {
            a0 = ffma2(r0[c], hp[c], a0);
            a1 = ffma2(r1[c], hp[c], a1);
            a2 = ffma2(r2[c], hp[c], a2);
            a3 = ffma2(r3[c], hp[c], a3);
        }
        const float2 u0 = unpack2(a0), u1 = unpack2(a1);
        const float2 u2 = unpack2(a2), u3 = unpack2(a3);
        const float v0 = fmaxf(u0.x + u0.y + b2s[o],     0.0f);
        const float v1 = fmaxf(u1.x + u1.y + b2s[o + 1], 0.0f);
        const float v2 = fmaxf(u2.x + u2.y + b2s[o + 2], 0.0f);
        const float v3 = fmaxf(u3.x + u3.y + b2s[o + 3], 0.0f);
        uint32_t p0, p1;
        asm("cvt.rn.f16x2.f32 %0, %1, %2;" : "=r"(p0) : "f"(v1), "f"(v0));
        asm("cvt.rn.f16x2.f32 %0, %1, %2;" : "=r"(p1) : "f"(v3), "f"(v2));
        *(uint2*)(fout + o) = make_uint2(p0, p1);
    }
}

// =================================================================
// K3: gather-max over 32 neighbors (fp16, exact) -> pt[b][n][384]
// =================================================================
__global__ __launch_bounds__(256) void maxpool_kernel(
    const __half* __restrict__ feat, const int* __restrict__ idx,
    __half* __restrict__ pt, int B)
{
    const int s = blockIdx.y, b = blockIdx.z;
    const int tid = threadIdx.x;
    const int w = tid >> 5, lane = tid & 31;
    const int n = blockIdx.x * 8 + w;

    const int ki = idx[((size_t)b * NPTS + n) * KNB + lane];
    const __half* fb = feat + (size_t)(s * B + b) * NPTS * 128;

    __half2 m01 = __float2half2_rn(0.0f);
    __half2 m23 = __float2half2_rn(0.0f);
#pragma unroll
    for (int k = 0; k < KNB; k++) {
        const int j = __shfl_sync(0xffffffffu, ki, k);
        const uint2 vv = *(const uint2*)(fb + (size_t)j * 128 + lane * 4);
        m01 = __hmax2(m01, *(const __half2*)&vv.x);
        m23 = __hmax2(m23, *(const __half2*)&vv.y);
    }
    const size_t ofs = ((size_t)b * NPTS + n) * 384 + s * 128 + lane * 4;
    *(uint2*)(pt + ofs) = make_uint2(*(const uint32_t*)&m01, *(const uint32_t*)&m23);
}

// =================================================================
// K4: mma.sync fp16 GEMM, pre-split hi/lo planes, cp.async.
// CTA 128x128, 4 warps (2x2, warp tile 64x64), 128 threads,
// k-chunk 32, 2-stage pipeline, 2 CTAs/SM.
// Xl == nullptr => single-plane B (2 products).
// =================================================================
#define KCH    32
#define PITCH  80
#define ATILE  (128 * PITCH)            // 10240 B
#define STG_B  (4 * ATILE)              // Ah|Al|Bh|Bl = 40960
#define SMEM_GEMM_BYTES (2 * STG_B)     // 81920

__global__ __launch_bounds__(128, 2) void gemm_mma(
    const __half* __restrict__ Wh, const __half* __restrict__ Wl,
    const float* __restrict__ bias,
    const __half* __restrict__ Xh, const __half* __restrict__ Xl,
    __half* __restrict__ Yh, __half* __restrict__ Yl,
    float* __restrict__ Yf, int M, int K)
{
    extern __shared__ __align__(16) char smem[];
    const uint32_t sb = smem_u32(smem);

    const int tid = threadIdx.x, wid = tid >> 5, lane = tid & 31;
    const int wm = wid & 1, wn = wid >> 1;           // 2 x 2 warp grid
    const int m0 = blockIdx.x * 128, n0 = blockIdx.y * 128;
    const int bi = blockIdx.z;
    const size_t xrow0 = (size_t)bi * NPTS + n0;
    const bool dual = (Xl != nullptr);

    const uint32_t aOff = (uint32_t)(wm * 64 + (lane & 7) + ((lane >> 3) & 1) * 8) * PITCH
                        + ((lane >> 4) & 1) * 16;
    const uint32_t bOff = (uint32_t)(wn * 64 + (lane & 7) + ((lane >> 4) & 1) * 8) * PITCH
                        + ((lane >> 3) & 1) * 16;

    float acc[4][8][4];
#pragma unroll
    for (int i = 0; i < 4; i++)
#pragma unroll
        for (int j = 0; j < 8; j++)
#pragma unroll
            for (int r = 0; r < 4; r++) acc[i][j][r] = 0.0f;

    const int nch = K / KCH;

    // one chunk into stage stg: A rows 128 (hi/lo), B rows 128 (hi[/lo])
    auto issue = [&](int ch, int stg) {
        const uint32_t sbase = sb + (uint32_t)stg * STG_B;
        const int kof = ch * KCH;
#pragma unroll
        for (int r = 0; r < 4; r++) {
            const int unit = tid + r * 128;          // 0..511
            const int row = unit >> 2, seg = unit & 3;
            const uint32_t d = sbase + (uint32_t)row * PITCH + seg * 16;
            const size_t aidx = (size_t)(m0 + row) * K + kof + seg * 8;
            const size_t bidx = (xrow0 + row) * K + kof + seg * 8;
            cp16(d,             Wh + aidx);
            cp16(d + ATILE,     Wl + aidx);
            cp16(d + 2 * ATILE, Xh + bidx);
            if (dual) cp16(d + 3 * ATILE, Xl + bidx);
        }
        asm volatile("cp.async.commit_group;" ::: "memory");
    };

    issue(0, 0);

    for (int ch = 0; ch < nch; ch++) {
        const int cur = ch & 1;
        const bool more = (ch + 1 < nch);
        if (more) issue(ch + 1, cur ^ 1);
        if (more) asm volatile("cp.async.wait_group 1;" ::: "memory");
        else      asm volatile("cp.async.wait_group 0;" ::: "memory");
        __syncthreads();

        const uint32_t aT = sb + (uint32_t)cur * STG_B + aOff;
        const uint32_t bT = sb + (uint32_t)cur * STG_B + 2 * ATILE + bOff;
#pragma unroll
        for (int ks = 0; ks < 2; ks++) {
            const uint32_t kso = ks * 32;
            // B fragments: 64 n-rows -> 8 ni frags (hi, and lo if dual)
            uint32_t bh[8][2], bl[8][2];
#pragma unroll
            for (int pr = 0; pr < 4; pr++) {
                const uint32_t bo = bT + (uint32_t)pr * (16 * PITCH) + kso;
                ldsm4(bh[pr * 2][0], bh[pr * 2][1], bh[pr * 2 + 1][0], bh[pr * 2 + 1][1], bo);
                if (dual)
                    ldsm4(bl[pr * 2][0], bl[pr * 2][1], bl[pr * 2 + 1][0], bl[pr * 2 + 1][1],
                          bo + ATILE);
            }
#pragma unroll
            for (int mih = 0; mih < 2; mih++) {
                uint32_t ah[2][4], al[2][4];
#pragma unroll
                for (int mi2 = 0; mi2 < 2; mi2++) {
                    const uint32_t ao = aT + (uint32_t)(mih * 2 + mi2) * (16 * PITCH) + kso;
                    ldsm4(ah[mi2][0], ah[mi2][1], ah[mi2][2], ah[mi2][3], ao);
                    ldsm4(al[mi2][0], al[mi2][1], al[mi2][2], al[mi2][3], ao + ATILE);
                }
#pragma unroll
                for (int mi2 = 0; mi2 < 2; mi2++)
#pragma unroll
                    for (int ni = 0; ni < 8; ni++) {
                        float* c = acc[mih * 2 + mi2][ni];
                        mma_f16(c, ah[mi2], bh[ni]);
                        mma_f16(c, al[mi2], bh[ni]);
                        if (dual) mma_f16(c, ah[mi2], bl[ni]);
                    }
            }
        }
        __syncthreads();
    }

    // epilogue
    const int g = lane >> 2, t2 = (lane & 3) * 2;
#pragma unroll
    for (int mi = 0; mi < 4; mi++) {
        const int mlo = m0 + wm * 64 + mi * 16 + g;
        const float bv0 = bias[mlo], bv1 = bias[mlo + 8];
#pragma unroll
        for (int ni = 0; ni < 8; ni++) {
            const int n = n0 + wn * 64 + ni * 8 + t2;
            const size_t r0 = ((size_t)bi * NPTS + n) * M;
            const size_t r1 = r0 + M;
            float vv[4];
            vv[0] = fmaxf(acc[mi][ni][0] + bv0, 0.0f);
            vv[1] = fmaxf(acc[mi][ni][1] + bv0, 0.0f);
            vv[2] = fmaxf(acc[mi][ni][2] + bv1, 0.0f);
            vv[3] = fmaxf(acc[mi][ni][3] + bv1, 0.0f);
            if (Yh) {
#pragma unroll
                for (int q = 0; q < 4; q++) {
                    const size_t o = (q & 1 ? r1 : r0) + mlo + (q >> 1) * 8;
                    const __half hb = __float2half_rn(vv[q]);
                    Yh[o] = hb;
                    Yl[o] = __float2half_rn(vv[q] - __half2float(hb));
                }
            }
            if (Yf) {
                Yf[r0 + mlo]     = vv[0];
                Yf[r1 + mlo]     = vv[1];
                Yf[r0 + mlo + 8] = vv[2];
                Yf[r1 + mlo + 8] = vv[3];
            }
        }
    }
}

// =================================================================
// rowmax on gf planes (hi+lo), two-phase
// =================================================================
__global__ __launch_bounds__(256) void rowmax_part(const __half* __restrict__ gh,
                                                   const __half* __restrict__ gl,
                                                   float* __restrict__ part)
{
    const int c = blockIdx.x * 256 + threadIdx.x;
    const int ns = blockIdx.y, b = blockIdx.z;
    const size_t base = ((size_t)b * NPTS + ns * 256) * 1024 + c;
    float m0 = -3.0e38f, m1 = -3.0e38f, m2 = -3.0e38f, m3 = -3.0e38f;
#pragma unroll 4
    for (int n = 0; n < 256; n += 4) {
        m0 = fmaxf(m0, __half2float(gh[base + (size_t)(n    ) * 1024]) +
                       __half2float(gl[base + (size_t)(n    ) * 1024]));
        m1 = fmaxf(m1, __half2float(gh[base + (size_t)(n + 1) * 1024]) +
                       __half2float(gl[base + (size_t)(n + 1) * 1024]));
        m2 = fmaxf(m2, __half2float(gh[base + (size_t)(n + 2) * 1024]) +
                       __half2float(gl[base + (size_t)(n + 2) * 1024]));
        m3 = fmaxf(m3, __half2float(gh[base + (size_t)(n + 3) * 1024]) +
                       __half2float(gl[base + (size_t)(n + 3) * 1024]));
    }
    part[(size_t)(b * 16 + ns) * 1024 + c] = fmaxf(fmaxf(m0, m1), fmaxf(m2, m3));
}

__global__ __launch_bounds__(256) void rowmax_fin(const float* __restrict__ part,
                                                  float* __restrict__ out)
{
    const int c = blockIdx.x * 256 + threadIdx.x;
    const int b = blockIdx.y;
    float m = -3.0e38f;
#pragma unroll
    for (int i = 0; i < 16; i++)
        m = fmaxf(m, part[(size_t)(b * 16 + i) * 1024 + c]);
    out[(size_t)b * 1024 + c] = m;
}

// =================================================================
// transpose msf_t[b][n][128] -> out[b][128][n]
// =================================================================
__global__ void transpose_msf(const float* __restrict__ in, float* __restrict__ out)
{
    __shared__ float t[32][33];
    const int b = blockIdx.z;
    const int n0 = blockIdx.x * 32, c0 = blockIdx.y * 32;
    const int tx = threadIdx.x, ty = threadIdx.y;
#pragma unroll
    for (int r = 0; r < 32; r += 8)
        t[ty + r][tx] = in[(size_t)((size_t)b * NPTS + n0 + ty + r) * 128 + c0 + tx];
    __syncthreads();
#pragma unroll
    for (int r = 0; r < 32; r += 8)
        out[(size_t)((size_t)b * 128 + c0 + ty + r) * NPTS + n0 + tx] = t[tx][ty + r];
}

// =================================================================
extern "C" void kernel_launch(void* const* d_in, const int* in_sizes, int n_in,
                              void* d_out, int out_size)
{
    const float* x   = (const float*)d_in[0];
    const float* sW0 = (const float*)d_in[1];
    const float* sb0 = (const float*)d_in[2];
    const float* sW1 = (const float*)d_in[3];
    const float* sb1 = (const float*)d_in[4];
    const float* sW2 = (const float*)d_in[5];
    const float* sb2 = (const float*)d_in[6];
    const float* gW0 = (const float*)d_in[7];
    const float* gb0 = (const float*)d_in[8];
    const float* gW1 = (const float*)d_in[9];
    const float* gb1 = (const float*)d_in[10];
    const float* mW0 = (const float*)d_in[11];
    const float* mb0 = (const float*)d_in[12];
    const float* mW1 = (const float*)d_in[13];
    const float* mb1 = (const float*)d_in[14];

    const int B = in_sizes[0] / (3 * NPTS);
    float* out = (float*)d_out;

    void *p_idx, *p_feat, *p_pt, *p_g0h, *p_g0l, *p_gfh, *p_gfl;
    void *p_m0h, *p_m0l, *p_msf, *p_part, *p_wh, *p_wl;
    cudaGetSymbolAddress(&p_idx,  g_idx);
    cudaGetSymbolAddress(&p_feat, g_feat);
    cudaGetSymbolAddress(&p_pt,   g_pt);
    cudaGetSymbolAddress(&p_g0h,  g_gf0_h);  cudaGetSymbolAddress(&p_g0l,  g_gf0_l);
    cudaGetSymbolAddress(&p_gfh,  g_gf_h);   cudaGetSymbolAddress(&p_gfl,  g_gf_l);
    cudaGetSymbolAddress(&p_m0h,  g_msf0_h); cudaGetSymbolAddress(&p_m0l,  g_msf0_l);
    cudaGetSymbolAddress(&p_msf,  g_msf_t);
    cudaGetSymbolAddress(&p_part, g_part);
    cudaGetSymbolAddress(&p_wh,   g_w_h);    cudaGetSymbolAddress(&p_wl,   g_w_l);

    __half* wh = (__half*)p_wh;
    __half* wl = (__half*)p_wl;

    cudaFuncSetAttribute(feat_kernel,
                         cudaFuncAttributeMaxDynamicSharedMemorySize, SMEM_FEAT_BYTES);
    cudaFuncSetAttribute(gemm_mma,
                         cudaFuncAttributeMaxDynamicSharedMemorySize, SMEM_GEMM_BYTES);

    // 0) split weights
    split_all<<<640, 256>>>(gW0, gW1, mW0, mW1, wh, wl);

    // 1) KNN
    knn_kernel<<<dim3(NPTS / 8, B), 256>>>(x, (int*)p_idx);

    // 2) per-point MLP features (fp16 plane)
    feat_kernel<<<dim3(NPTS / 128, 3, B), 128, SMEM_FEAT_BYTES>>>(
        x, sW0, sb0, sW1, sb1, sW2, sb2, (__half*)p_feat, B);

    // 3) gather-max -> pt[b][n][384]
    maxpool_kernel<<<dim3(NPTS / 8, 3, B), 256>>>(
        (const __half*)p_feat, (const int*)p_idx, (__half*)p_pt, B);

    // 4) gf0 = relu(gW0 @ point)   M=256,K=384  (single-plane B)
    gemm_mma<<<dim3(2, NPTS / 128, B), 128, SMEM_GEMM_BYTES>>>(
        wh + OFF_G0, wl + OFF_G0, gb0,
        (const __half*)p_pt, nullptr,
        (__half*)p_g0h, (__half*)p_g0l, nullptr, 256, 384);

    // 5) gf = relu(gW1 @ gf0)      M=1024,K=256
    gemm_mma<<<dim3(8, NPTS / 128, B), 128, SMEM_GEMM_BYTES>>>(
        wh + OFF_G1, wl + OFF_G1, gb1,
        (const __half*)p_g0h, (const __half*)p_g0l,
        (__half*)p_gfh, (__half*)p_gfl, nullptr, 1024, 256);

    // 6) global_feature -> d_out[0 : B*1024]
    rowmax_part<<<dim3(4, 16, B), 256>>>(
        (const __half*)p_gfh, (const __half*)p_gfl, (float*)p_part);
    rowmax_fin<<<dim3(4, B), 256>>>((const float*)p_part, out);

    // 7) msf0 = relu(mW0 @ gf)     M=256,K=1024
    gemm_mma<<<dim3(2, NPTS / 128, B), 128, SMEM_GEMM_BYTES>>>(
        wh + OFF_M0, wl + OFF_M0, mb0,
        (const __half*)p_gfh, (const __half*)p_gfl,
        (__half*)p_m0h, (__half*)p_m0l, nullptr, 256, 1024);

    // 8) msf = relu(mW1 @ msf0)    M=128,K=256 (fp32 out)
    gemm_mma<<<dim3(1, NPTS / 128, B), 128, SMEM_GEMM_BYTES>>>(
        wh + OFF_M1, wl + OFF_M1, mb1,
        (const __half*)p_m0h, (const __half*)p_m0l,
        nullptr, nullptr, (float*)p_msf, 128, 256);

    // 9) transpose -> d_out[B*1024 : ] as [B,128,N]
    transpose_msf<<<dim3(NPTS / 32, 128 / 32, B), dim3(32, 8)>>>(
        (const float*)p_msf, out + (size_t)B * 1024);
}

// round 15
// speedup vs baseline: 1.3309x; 1.2206x over previous
#include <cuda_runtime.h>
#include <cuda_bf16.h>
#include <cuda_fp16.h>
#include <cstdint>

#define NPTS 4096
#define KNB  32
#define BMAX 4

typedef unsigned long long ull;

// ---------------- f32x2 helpers (feat kernel) ----------------
__device__ __forceinline__ ull pack2(float lo, float hi) {
    ull r; asm("mov.b64 %0, {%1, %2};" : "=l"(r) : "f"(lo), "f"(hi)); return r;
}
__device__ __forceinline__ ull ffma2(ull a, ull b, ull c) {
    ull d; asm("fma.rn.f32x2 %0, %1, %2, %3;" : "=l"(d) : "l"(a), "l"(b), "l"(c));
    return d;
}
__device__ __forceinline__ float2 unpack2(ull v) {
    float lo, hi; asm("mov.b64 {%0, %1}, %2;" : "=f"(lo), "=f"(hi) : "l"(v));
    return make_float2(lo, hi);
}

// ---------------- fp16 split + mma helpers ----------------
__device__ __forceinline__ void cvt_split4h(const float* v, uint32_t* h, uint32_t* l) {
#pragma unroll
    for (int j = 0; j < 2; j++) {
        uint32_t hh;
        asm("cvt.rn.f16x2.f32 %0, %1, %2;" : "=r"(hh) : "f"(v[2 * j + 1]), "f"(v[2 * j]));
        const __half2 hv = *(const __half2*)&hh;
        const float f0 = __low2float(hv), f1 = __high2float(hv);
        uint32_t ll;
        asm("cvt.rn.f16x2.f32 %0, %1, %2;" : "=r"(ll)
            : "f"(v[2 * j + 1] - f1), "f"(v[2 * j] - f0));
        h[j] = hh; l[j] = ll;
    }
}
__device__ __forceinline__ void mma_f16(float* c, const uint32_t* a, const uint32_t* b) {
    asm volatile(
        "mma.sync.aligned.m16n8k16.row.col.f32.f16.f16.f32 "
        "{%0,%1,%2,%3}, {%4,%5,%6,%7}, {%8,%9}, {%0,%1,%2,%3};"
        : "+f"(c[0]), "+f"(c[1]), "+f"(c[2]), "+f"(c[3])
        : "r"(a[0]), "r"(a[1]), "r"(a[2]), "r"(a[3]), "r"(b[0]), "r"(b[1]));
}
__device__ __forceinline__ void ldsm4(uint32_t& r0, uint32_t& r1, uint32_t& r2, uint32_t& r3,
                                      uint32_t addr) {
    asm volatile("ldmatrix.sync.aligned.m8n8.x4.shared.b16 {%0,%1,%2,%3}, [%4];"
                 : "=r"(r0), "=r"(r1), "=r"(r2), "=r"(r3) : "r"(addr));
}
__device__ __forceinline__ uint32_t smem_u32(const void* p) {
    uint32_t a;
    asm("{ .reg .u64 t; cvta.to.shared.u64 t, %1; cvt.u32.u64 %0, t; }" : "=r"(a) : "l"(p));
    return a;
}
__device__ __forceinline__ void cp16(uint32_t dst, const void* src) {
    asm volatile("cp.async.ca.shared.global [%0], [%1], 16;" :: "r"(dst), "l"(src));
}

// ---------------- scratch ----------------
__device__ __align__(16) int    g_idx   [BMAX * NPTS * KNB];
__device__ __align__(16) __half g_feat  [(size_t)3 * BMAX * NPTS * 128];
__device__ __align__(16) __half g_pt    [(size_t)BMAX * NPTS * 384];
__device__ __align__(16) __half g_gf0   [(size_t)BMAX * NPTS * 256];
__device__ __align__(16) __half g_gf    [(size_t)BMAX * NPTS * 1024];
__device__ __align__(16) __half g_msf0  [(size_t)BMAX * NPTS * 256];
__device__ __align__(16) float  g_msf_t [(size_t)BMAX * NPTS * 128];
__device__ __align__(16) float  g_part  [BMAX * 16 * 1024];
__device__ __align__(16) __half g_w_h   [655360];
__device__ __align__(16) __half g_w_l   [655360];

#define OFF_G0 0
#define OFF_G1 98304
#define OFF_M0 360448
#define OFF_M1 622592

// =================================================================
// K0: split all 4 weight matrices fp32 -> fp16 hi/lo, one launch
// =================================================================
__global__ __launch_bounds__(256) void split_all(
    const float* __restrict__ g0, const float* __restrict__ g1,
    const float* __restrict__ m0, const float* __restrict__ m1,
    __half* __restrict__ wh, __half* __restrict__ wl)
{
    int blk = blockIdx.x;
    const float* src; int base;
    if (blk < 96)       { src = g0; base = OFF_G0; }
    else if (blk < 352) { src = g1; base = OFF_G1; blk -= 96; }
    else if (blk < 608) { src = m0; base = OFF_M0; blk -= 352; }
    else                { src = m1; base = OFF_M1; blk -= 608; }
    const int i = (blk * 256 + threadIdx.x) * 4;
    const float4 v = *(const float4*)(src + i);
    uint32_t hh[2], ll[2];
    cvt_split4h(&v.x, hh, ll);
    *(uint2*)(wh + base + i) = make_uint2(hh[0], hh[1]);
    *(uint2*)(wl + base + i) = make_uint2(ll[0], ll[1]);
}

// =================================================================
// K1: KNN — warp per query, lane-distributed sorted top-32 list
// =================================================================
__global__ __launch_bounds__(256) void knn_kernel(const float* __restrict__ x,
                                                  int* __restrict__ idx)
{
    __shared__ float4 tile[1024];
    const int b = blockIdx.y;
    const int tid = threadIdx.x;
    const int w = tid >> 5, lane = tid & 31;
    const int q = blockIdx.x * 8 + w;
    const float* xb = x + (size_t)b * 3 * NPTS;

    const float qx = xb[q], qy = xb[NPTS + q], qz = xb[2 * NPTS + q];
    const float qsq = qx * qx + qy * qy + qz * qz;

    float v = 3.0e38f;
    int   vi = 0x7fffffff;
    float cm = 3.0e38f;

    for (int t0 = 0; t0 < NPTS; t0 += 1024) {
        __syncthreads();
        for (int i = tid; i < 1024; i += 256) {
            const int g = t0 + i;
            const float cx = xb[g], cy = xb[NPTS + g], cz = xb[2 * NPTS + g];
            tile[i] = make_float4(cx, cy, cz, cx * cx + cy * cy + cz * cz);
        }
        __syncthreads();

        for (int c = 0; c < 32; c++) {
            const int gbase = t0 + c * 32;
            const float4 p = tile[c * 32 + lane];
            float d = qsq + p.w - 2.0f * fmaf(qx, p.x, fmaf(qy, p.y, qz * p.z));
            if (gbase + lane == q) d = 3.0e38f;

            unsigned m = __ballot_sync(0xffffffffu, d < cm);
            while (m) {
                const int src = __ffs(m) - 1; m &= m - 1;
                const float dd = __shfl_sync(0xffffffffu, d, src);
                const int   ii = gbase + src;
                const unsigned less = __ballot_sync(0xffffffffu,
                        (v < dd) || (v == dd && vi < ii));
                const int pos = __popc(less);
                const float pv = __shfl_up_sync(0xffffffffu, v, 1);
                const int   pi = __shfl_up_sync(0xffffffffu, vi, 1);
                if (pos < 32) {
                    if (lane == pos)      { v = dd; vi = ii; }
                    else if (lane > pos)  { v = pv; vi = pi; }
                }
                cm = __shfl_sync(0xffffffffu, v, 31);
            }
        }
    }
    idx[((size_t)b * NPTS + q) * KNB + lane] = vi;
}

// =================================================================
// K2: per-point 3-layer MLP (3->64->64->128), f32x2 math, fp16 out
// =================================================================
#define SMEM_FEAT_FLOATS (192 + 64 + 4096 + 64 + 8192 + 128)
#define SMEM_FEAT_BYTES  (SMEM_FEAT_FLOATS * 4)

__global__ __launch_bounds__(128) void feat_kernel(
    const float* __restrict__ x,
    const float* __restrict__ sW0, const float* __restrict__ sb0,
    const float* __restrict__ sW1, const float* __restrict__ sb1,
    const float* __restrict__ sW2, const float* __restrict__ sb2,
    __half* __restrict__ feat, int B)
{
    extern __shared__ float sm[];
    float* w0s = sm;
    float* b0s = w0s + 192;
    float* w1s = b0s + 64;
    float* b1s = w1s + 4096;
    float* w2s = b1s + 64;
    float* b2s = w2s + 8192;

    const int s = blockIdx.y, b = blockIdx.z;
    const int tid = threadIdx.x;

    for (int i = tid; i < 192;  i += 128) w0s[i] = sW0[s * 192 + i];
    for (int i = tid; i < 64;   i += 128) { b0s[i] = sb0[s * 64 + i]; b1s[i] = sb1[s * 64 + i]; }
    for (int i = tid; i < 4096; i += 128) w1s[i] = sW1[s * 4096 + i];
    for (int i = tid; i < 8192; i += 128) w2s[i] = sW2[s * 8192 + i];
    for (int i = tid; i < 128;  i += 128) b2s[i] = sb2[s * 128 + i];
    __syncthreads();

    const int j = blockIdx.x * 128 + tid;
    const float* xb = x + (size_t)b * 3 * NPTS;
    const float px = xb[j], py = xb[NPTS + j], pz = xb[2 * NPTS + j];

    float h0[64];
#pragma unroll
    for (int o = 0; o < 64; o++) {
        float a = fmaf(w0s[o * 3 + 2], pz,
                  fmaf(w0s[o * 3 + 1], py,
                  fmaf(w0s[o * 3 + 0], px, b0s[o])));
        h0[o] = fmaxf(a, 0.0f);
    }

    ull hp[32];
#pragma unroll
    for (int c = 0; c < 32; c++) hp[c] = pack2(h0[2 * c], h0[2 * c + 1]);

    float h1[64];
#pragma unroll
    for (int o = 0; o < 64; o += 2) {
        ull a0 = 0ull, a1 = 0ull;
        const ull* r0 = (const ull*)(w1s + (o    ) * 64);
        const ull* r1 = (const ull*)(w1s + (o + 1) * 64);
#pragma unroll
        for (int c = 0; c < 32; c++) {
            a0 = ffma2(r0[c], hp[c], a0);
            a1 = ffma2(r1[c], hp[c], a1);
        }
        const float2 u0 = unpack2(a0), u1 = unpack2(a1);
        h1[o]     = fmaxf(u0.x + u0.y + b1s[o],     0.0f);
        h1[o + 1] = fmaxf(u1.x + u1.y + b1s[o + 1], 0.0f);
    }

#pragma unroll
    for (int c = 0; c < 32; c++) hp[c] = pack2(h1[2 * c], h1[2 * c + 1]);

    __half* fout = feat + ((size_t)(s * B + b) * NPTS + j) * 128;
    for (int o = 0; o < 128; o += 4) {
        ull a0 = 0ull, a1 = 0ull, a2 = 0ull, a3 = 0ull;
        const ull* r0 = (const ull*)(w2s + (size_t)(o    ) * 64);
        const ull* r1 = (const ull*)(w2s + (size_t)(o + 1) * 64);
        const ull* r2 = (const ull*)(w2s + (size_t)(o + 2) * 64);
        const ull* r3 = (const ull*)(w2s + (size_t)(o + 3) * 64);
#pragma unroll
        for (int c = 0; c < 32; c++) {
            a0 = ffma2(r0[c], hp[c], a0);
            a1 = ffma2(r1[c], hp[c], a1);
            a2 = ffma2(r2[c], hp[c], a2);
            a3 = ffma2(r3[c], hp[c], a3);
        }
        const float2 u0 = unpack2(a0), u1 = unpack2(a1);
        const float2 u2 = unpack2(a2), u3 = unpack2(a3);
        const float v0 = fmaxf(u0.x + u0.y + b2s[o],     0.0f);
        const float v1 = fmaxf(u1.x + u1.y + b2s[o + 1], 0.0f);
        const float v2 = fmaxf(u2.x + u2.y + b2s[o + 2], 0.0f);
        const float v3 = fmaxf(u3.x + u3.y + b2s[o + 3], 0.0f);
        uint32_t p0, p1;
        asm("cvt.rn.f16x2.f32 %0, %1, %2;" : "=r"(p0) : "f"(v1), "f"(v0));
        asm("cvt.rn.f16x2.f32 %0, %1, %2;" : "=r"(p1) : "f"(v3), "f"(v2));
        *(uint2*)(fout + o) = make_uint2(p0, p1);
    }
}

// =================================================================
// K3: gather-max over 32 neighbors (fp16, exact) -> pt[b][n][384]
// =================================================================
__global__ __launch_bounds__(256) void maxpool_kernel(
    const __half* __restrict__ feat, const int* __restrict__ idx,
    __half* __restrict__ pt, int B)
{
    const int s = blockIdx.y, b = blockIdx.z;
    const int tid = threadIdx.x;
    const int w = tid >> 5, lane = tid & 31;
    const int n = blockIdx.x * 8 + w;

    const int ki = idx[((size_t)b * NPTS + n) * KNB + lane];
    const __half* fb = feat + (size_t)(s * B + b) * NPTS * 128;

    __half2 m01 = __float2half2_rn(0.0f);
    __half2 m23 = __float2half2_rn(0.0f);
#pragma unroll
    for (int k = 0; k < KNB; k++) {
        const int j = __shfl_sync(0xffffffffu, ki, k);
        const uint2 vv = *(const uint2*)(fb + (size_t)j * 128 + lane * 4);
        m01 = __hmax2(m01, *(const __half2*)&vv.x);
        m23 = __hmax2(m23, *(const __half2*)&vv.y);
    }
    const size_t ofs = ((size_t)b * NPTS + n) * 384 + s * 128 + lane * 4;
    *(uint2*)(pt + ofs) = make_uint2(*(const uint32_t*)&m01, *(const uint32_t*)&m23);
}

// =================================================================
// K4: mma.sync fp16 GEMM. Weights hi/lo dual, activations single
// fp16 plane => 2 products per tile. cp.async 2-stage pipeline.
// CTA 128x128, 4 warps (2x2, warp tile 64x64), 128 threads,
// k-chunk 32, 2 CTAs/SM.
// =================================================================
#define KCH    32
#define PITCH  80
#define ATILE  (128 * PITCH)            // 10240 B
#define STG_B  (3 * ATILE)              // Ah|Al|Bh = 30720
#define SMEM_GEMM_BYTES (2 * STG_B)     // 61440

__global__ __launch_bounds__(128, 2) void gemm_mma(
    const __half* __restrict__ Wh, const __half* __restrict__ Wl,
    const float* __restrict__ bias,
    const __half* __restrict__ Xh,
    __half* __restrict__ Yh, float* __restrict__ Yf, int M, int K)
{
    extern __shared__ __align__(16) char smem[];
    const uint32_t sb = smem_u32(smem);

    const int tid = threadIdx.x, wid = tid >> 5, lane = tid & 31;
    const int wm = wid & 1, wn = wid >> 1;           // 2 x 2 warp grid
    const int m0 = blockIdx.x * 128, n0 = blockIdx.y * 128;
    const int bi = blockIdx.z;
    const size_t xrow0 = (size_t)bi * NPTS + n0;

    const uint32_t aOff = (uint32_t)(wm * 64 + (lane & 7) + ((lane >> 3) & 1) * 8) * PITCH
                        + ((lane >> 4) & 1) * 16;
    const uint32_t bOff = (uint32_t)(wn * 64 + (lane & 7) + ((lane >> 4) & 1) * 8) * PITCH
                        + ((lane >> 3) & 1) * 16;

    float acc[4][8][4];
#pragma unroll
    for (int i = 0; i < 4; i++)
#pragma unroll
        for (int j = 0; j < 8; j++)
#pragma unroll
            for (int r = 0; r < 4; r++) acc[i][j][r] = 0.0f;

    const int nch = K / KCH;

    auto issue = [&](int ch, int stg) {
        const uint32_t sbase = sb + (uint32_t)stg * STG_B;
        const int kof = ch * KCH;
#pragma unroll
        for (int r = 0; r < 4; r++) {
            const int unit = tid + r * 128;
            const int row = unit >> 2, seg = unit & 3;
            const uint32_t d = sbase + (uint32_t)row * PITCH + seg * 16;
            const size_t aidx = (size_t)(m0 + row) * K + kof + seg * 8;
            const size_t bidx = (xrow0 + row) * K + kof + seg * 8;
            cp16(d,             Wh + aidx);
            cp16(d + ATILE,     Wl + aidx);
            cp16(d + 2 * ATILE, Xh + bidx);
        }
        asm volatile("cp.async.commit_group;" ::: "memory");
    };

    issue(0, 0);

    for (int ch = 0; ch < nch; ch++) {
        const int cur = ch & 1;
        const bool more = (ch + 1 < nch);
        if (more) issue(ch + 1, cur ^ 1);
        if (more) asm volatile("cp.async.wait_group 1;" ::: "memory");
        else      asm volatile("cp.async.wait_group 0;" ::: "memory");
        __syncthreads();

        const uint32_t aT = sb + (uint32_t)cur * STG_B + aOff;
        const uint32_t bT = sb + (uint32_t)cur * STG_B + 2 * ATILE + bOff;
#pragma unroll
        for (int ks = 0; ks < 2; ks++) {
            const uint32_t kso = ks * 32;
            uint32_t bh[8][2];
#pragma unroll
            for (int pr = 0; pr < 4; pr++) {
                const uint32_t bo = bT + (uint32_t)pr * (16 * PITCH) + kso;
                ldsm4(bh[pr * 2][0], bh[pr * 2][1], bh[pr * 2 + 1][0], bh[pr * 2 + 1][1], bo);
            }
#pragma unroll
            for (int mih = 0; mih < 2; mih++) {
                uint32_t ah[2][4], al[2][4];
#pragma unroll
                for (int mi2 = 0; mi2 < 2; mi2++) {
                    const uint32_t ao = aT + (uint32_t)(mih * 2 + mi2) * (16 * PITCH) + kso;
                    ldsm4(ah[mi2][0], ah[mi2][1], ah[mi2][2], ah[mi2][3], ao);
                    ldsm4(al[mi2][0], al[mi2][1], al[mi2][2], al[mi2][3], ao + ATILE);
                }
#pragma unroll
                for (int mi2 = 0; mi2 < 2; mi2++)
#pragma unroll
                    for (int ni = 0; ni < 8; ni++) {
                        float* c = acc[mih * 2 + mi2][ni];
                        mma_f16(c, ah[mi2], bh[ni]);
                        mma_f16(c, al[mi2], bh[ni]);
                    }
            }
        }
        __syncthreads();
    }

    // epilogue
    const int g = lane >> 2, t2 = (lane & 3) * 2;
#pragma unroll
    for (int mi = 0; mi < 4; mi++) {
        const int mlo = m0 + wm * 64 + mi * 16 + g;
        const float bv0 = bias[mlo], bv1 = bias[mlo + 8];
#pragma unroll
        for (int ni = 0; ni < 8; ni++) {
            const int n = n0 + wn * 64 + ni * 8 + t2;
            const size_t r0 = ((size_t)bi * NPTS + n) * M;
            const size_t r1 = r0 + M;
            const float v0 = fmaxf(acc[mi][ni][0] + bv0, 0.0f);
            const float v1 = fmaxf(acc[mi][ni][1] + bv0, 0.0f);
            const float v2 = fmaxf(acc[mi][ni][2] + bv1, 0.0f);
            const float v3 = fmaxf(acc[mi][ni][3] + bv1, 0.0f);
            if (Yh) {
                Yh[r0 + mlo]     = __float2half_rn(v0);
                Yh[r1 + mlo]     = __float2half_rn(v1);
                Yh[r0 + mlo + 8] = __float2half_rn(v2);
                Yh[r1 + mlo + 8] = __float2half_rn(v3);
            } else {
                Yf[r0 + mlo]     = v0;
                Yf[r1 + mlo]     = v1;
                Yf[r0 + mlo + 8] = v2;
                Yf[r1 + mlo + 8] = v3;
            }
        }
    }
}

// =================================================================
// rowmax on gf (fp16), two-phase
// =================================================================
__global__ __launch_bounds__(256) void rowmax_part(const __half* __restrict__ gf,
                                                   float* __restrict__ part)
{
    const int c = blockIdx.x * 256 + threadIdx.x;
    const int ns = blockIdx.y, b = blockIdx.z;
    const size_t base = ((size_t)b * NPTS + ns * 256) * 1024 + c;
    __half m0 = __float2half_rn(0.0f), m1 = m0, m2 = m0, m3 = m0;   // relu => >= 0
#pragma unroll 4
    for (int n = 0; n < 256; n += 4) {
        m0 = __hmax(m0, gf[base + (size_t)(n    ) * 1024]);
        m1 = __hmax(m1, gf[base + (size_t)(n + 1) * 1024]);
        m2 = __hmax(m2, gf[base + (size_t)(n + 2) * 1024]);
        m3 = __hmax(m3, gf[base + (size_t)(n + 3) * 1024]);
    }
    part[(size_t)(b * 16 + ns) * 1024 + c] =
        __half2float(__hmax(__hmax(m0, m1), __hmax(m2, m3)));
}

__global__ __launch_bounds__(256) void rowmax_fin(const float* __restrict__ part,
                                                  float* __restrict__ out)
{
    const int c = blockIdx.x * 256 + threadIdx.x;
    const int b = blockIdx.y;
    float m = -3.0e38f;
#pragma unroll
    for (int i = 0; i < 16; i++)
        m = fmaxf(m, part[(size_t)(b * 16 + i) * 1024 + c]);
    out[(size_t)b * 1024 + c] = m;
}

// =================================================================
// transpose msf_t[b][n][128] -> out[b][128][n]
// =================================================================
__global__ void transpose_msf(const float* __restrict__ in, float* __restrict__ out)
{
    __shared__ float t[32][33];
    const int b = blockIdx.z;
    const int n0 = blockIdx.x * 32, c0 = blockIdx.y * 32;
    const int tx = threadIdx.x, ty = threadIdx.y;
#pragma unroll
    for (int r = 0; r < 32; r += 8)
        t[ty + r][tx] = in[(size_t)((size_t)b * NPTS + n0 + ty + r) * 128 + c0 + tx];
    __syncthreads();
#pragma unroll
    for (int r = 0; r < 32; r += 8)
        out[(size_t)((size_t)b * 128 + c0 + ty + r) * NPTS + n0 + tx] = t[tx][ty + r];
}

// =================================================================
extern "C" void kernel_launch(void* const* d_in, const int* in_sizes, int n_in,
                              void* d_out, int out_size)
{
    const float* x   = (const float*)d_in[0];
    const float* sW0 = (const float*)d_in[1];
    const float* sb0 = (const float*)d_in[2];
    const float* sW1 = (const float*)d_in[3];
    const float* sb1 = (const float*)d_in[4];
    const float* sW2 = (const float*)d_in[5];
    const float* sb2 = (const float*)d_in[6];
    const float* gW0 = (const float*)d_in[7];
    const float* gb0 = (const float*)d_in[8];
    const float* gW1 = (const float*)d_in[9];
    const float* gb1 = (const float*)d_in[10];
    const float* mW0 = (const float*)d_in[11];
    const float* mb0 = (const float*)d_in[12];
    const float* mW1 = (const float*)d_in[13];
    const float* mb1 = (const float*)d_in[14];

    const int B = in_sizes[0] / (3 * NPTS);
    float* out = (float*)d_out;

    void *p_idx, *p_feat, *p_pt, *p_g0, *p_gf, *p_m0, *p_msf, *p_part, *p_wh, *p_wl;
    cudaGetSymbolAddress(&p_idx,  g_idx);
    cudaGetSymbolAddress(&p_feat, g_feat);
    cudaGetSymbolAddress(&p_pt,   g_pt);
    cudaGetSymbolAddress(&p_g0,   g_gf0);
    cudaGetSymbolAddress(&p_gf,   g_gf);
    cudaGetSymbolAddress(&p_m0,   g_msf0);
    cudaGetSymbolAddress(&p_msf,  g_msf_t);
    cudaGetSymbolAddress(&p_part, g_part);
    cudaGetSymbolAddress(&p_wh,   g_w_h);
    cudaGetSymbolAddress(&p_wl,   g_w_l);

    __half* wh = (__half*)p_wh;
    __half* wl = (__half*)p_wl;

    cudaFuncSetAttribute(feat_kernel,
                         cudaFuncAttributeMaxDynamicSharedMemorySize, SMEM_FEAT_BYTES);
    cudaFuncSetAttribute(gemm_mma,
                         cudaFuncAttributeMaxDynamicSharedMemorySize, SMEM_GEMM_BYTES);

    // 0) split weights
    split_all<<<640, 256>>>(gW0, gW1, mW0, mW1, wh, wl);

    // 1) KNN
    knn_kernel<<<dim3(NPTS / 8, B), 256>>>(x, (int*)p_idx);

    // 2) per-point MLP features (fp16 plane)
    feat_kernel<<<dim3(NPTS / 128, 3, B), 128, SMEM_FEAT_BYTES>>>(
        x, sW0, sb0, sW1, sb1, sW2, sb2, (__half*)p_feat, B);

    // 3) gather-max -> pt[b][n][384]
    maxpool_kernel<<<dim3(NPTS / 8, 3, B), 256>>>(
        (const __half*)p_feat, (const int*)p_idx, (__half*)p_pt, B);

    // 4) gf0 = relu(gW0 @ point)   M=256,K=384
    gemm_mma<<<dim3(2, NPTS / 128, B), 128, SMEM_GEMM_BYTES>>>(
        wh + OFF_G0, wl + OFF_G0, gb0, (const __half*)p_pt,
        (__half*)p_g0, nullptr, 256, 384);

    // 5) gf = relu(gW1 @ gf0)      M=1024,K=256
    gemm_mma<<<dim3(8, NPTS / 128, B), 128, SMEM_GEMM_BYTES>>>(
        wh + OFF_G1, wl + OFF_G1, gb1, (const __half*)p_g0,
        (__half*)p_gf, nullptr, 1024, 256);

    // 6) global_feature -> d_out[0 : B*1024]
    rowmax_part<<<dim3(4, 16, B), 256>>>((const __half*)p_gf, (float*)p_part);
    rowmax_fin<<<dim3(4, B), 256>>>((const float*)p_part, out);

    // 7) msf0 = relu(mW0 @ gf)     M=256,K=1024
    gemm_mma<<<dim3(2, NPTS / 128, B), 128, SMEM_GEMM_BYTES>>>(
        wh + OFF_M0, wl + OFF_M0, mb0, (const __half*)p_gf,
        (__half*)p_m0, nullptr, 256, 1024);

    // 8) msf = relu(mW1 @ msf0)    M=128,K=256 (fp32 out)
    gemm_mma<<<dim3(1, NPTS / 128, B), 128, SMEM_GEMM_BYTES>>>(
        wh + OFF_M1, wl + OFF_M1, mb1, (const __half*)p_m0,
        nullptr, (float*)p_msf, 128, 256);

    // 9) transpose -> d_out[B*1024 : ] as [B,128,N]
    transpose_msf<<<dim3(NPTS / 32, 128 / 32, B), dim3(32, 8)>>>(
        (const float*)p_msf, out + (size_t)B * 1024);
}

// round 16
// speedup vs baseline: 1.5113x; 1.1355x over previous
#include <cuda_runtime.h>
#include <cuda_bf16.h>
#include <cuda_fp16.h>
#include <cstdint>

#define NPTS 4096
#define KNB  32
#define BMAX 4

typedef unsigned long long ull;

// ---------------- f32x2 helpers (feat kernel) ----------------
__device__ __forceinline__ ull pack2(float lo, float hi) {
    ull r; asm("mov.b64 %0, {%1, %2};" : "=l"(r) : "f"(lo), "f"(hi)); return r;
}
__device__ __forceinline__ ull ffma2(ull a, ull b, ull c) {
    ull d; asm("fma.rn.f32x2 %0, %1, %2, %3;" : "=l"(d) : "l"(a), "l"(b), "l"(c));
    return d;
}
__device__ __forceinline__ float2 unpack2(ull v) {
    float lo, hi; asm("mov.b64 {%0, %1}, %2;" : "=f"(lo), "=f"(hi) : "l"(v));
    return make_float2(lo, hi);
}

// ---------------- fp16 mma helpers ----------------
__device__ __forceinline__ void mma_f16(float* c, const uint32_t* a, const uint32_t* b) {
    asm volatile(
        "mma.sync.aligned.m16n8k16.row.col.f32.f16.f16.f32 "
        "{%0,%1,%2,%3}, {%4,%5,%6,%7}, {%8,%9}, {%0,%1,%2,%3};"
        : "+f"(c[0]), "+f"(c[1]), "+f"(c[2]), "+f"(c[3])
        : "r"(a[0]), "r"(a[1]), "r"(a[2]), "r"(a[3]), "r"(b[0]), "r"(b[1]));
}
__device__ __forceinline__ void ldsm4(uint32_t& r0, uint32_t& r1, uint32_t& r2, uint32_t& r3,
                                      uint32_t addr) {
    asm volatile("ldmatrix.sync.aligned.m8n8.x4.shared.b16 {%0,%1,%2,%3}, [%4];"
                 : "=r"(r0), "=r"(r1), "=r"(r2), "=r"(r3) : "r"(addr));
}
__device__ __forceinline__ uint32_t smem_u32(const void* p) {
    uint32_t a;
    asm("{ .reg .u64 t; cvta.to.shared.u64 t, %1; cvt.u32.u64 %0, t; }" : "=r"(a) : "l"(p));
    return a;
}
__device__ __forceinline__ void cp16(uint32_t dst, const void* src) {
    asm volatile("cp.async.ca.shared.global [%0], [%1], 16;" :: "r"(dst), "l"(src));
}

// ---------------- scratch ----------------
__device__ __align__(16) int    g_idx   [BMAX * NPTS * KNB];
__device__ __align__(16) __half g_feat  [(size_t)3 * BMAX * NPTS * 128];
__device__ __align__(16) __half g_pt    [(size_t)BMAX * NPTS * 384];
__device__ __align__(16) __half g_gf0   [(size_t)BMAX * NPTS * 256];
__device__ __align__(16) __half g_gf    [(size_t)BMAX * NPTS * 1024];
__device__ __align__(16) __half g_msf0  [(size_t)BMAX * NPTS * 256];
__device__ __align__(16) float  g_msf_t [(size_t)BMAX * NPTS * 128];
__device__ __align__(16) float  g_part  [BMAX * 16 * 1024];
__device__ __align__(16) __half g_w_h   [655360];

#define OFF_G0 0
#define OFF_G1 98304
#define OFF_M0 360448
#define OFF_M1 622592

// =================================================================
// K0: convert all 4 weight matrices fp32 -> fp16, one launch
// =================================================================
__global__ __launch_bounds__(256) void split_all(
    const float* __restrict__ g0, const float* __restrict__ g1,
    const float* __restrict__ m0, const float* __restrict__ m1,
    __half* __restrict__ wh)
{
    int blk = blockIdx.x;
    const float* src; int base;
    if (blk < 96)       { src = g0; base = OFF_G0; }
    else if (blk < 352) { src = g1; base = OFF_G1; blk -= 96; }
    else if (blk < 608) { src = m0; base = OFF_M0; blk -= 352; }
    else                { src = m1; base = OFF_M1; blk -= 608; }
    const int i = (blk * 256 + threadIdx.x) * 4;
    const float4 v = *(const float4*)(src + i);
    uint32_t p0, p1;
    asm("cvt.rn.f16x2.f32 %0, %1, %2;" : "=r"(p0) : "f"(v.y), "f"(v.x));
    asm("cvt.rn.f16x2.f32 %0, %1, %2;" : "=r"(p1) : "f"(v.w), "f"(v.z));
    *(uint2*)(wh + base + i) = make_uint2(p0, p1);
}

// =================================================================
// K1: KNN — warp per query, lane-distributed sorted top-32 list
// =================================================================
__global__ __launch_bounds__(256) void knn_kernel(const float* __restrict__ x,
                                                  int* __restrict__ idx)
{
    __shared__ float4 tile[1024];
    const int b = blockIdx.y;
    const int tid = threadIdx.x;
    const int w = tid >> 5, lane = tid & 31;
    const int q = blockIdx.x * 8 + w;
    const float* xb = x + (size_t)b * 3 * NPTS;

    const float qx = xb[q], qy = xb[NPTS + q], qz = xb[2 * NPTS + q];
    const float qsq = qx * qx + qy * qy + qz * qz;

    float v = 3.0e38f;
    int   vi = 0x7fffffff;
    float cm = 3.0e38f;

    for (int t0 = 0; t0 < NPTS; t0 += 1024) {
        __syncthreads();
        for (int i = tid; i < 1024; i += 256) {
            const int g = t0 + i;
            const float cx = xb[g], cy = xb[NPTS + g], cz = xb[2 * NPTS + g];
            tile[i] = make_float4(cx, cy, cz, cx * cx + cy * cy + cz * cz);
        }
        __syncthreads();

        for (int c = 0; c < 32; c++) {
            const int gbase = t0 + c * 32;
            const float4 p = tile[c * 32 + lane];
            float d = qsq + p.w - 2.0f * fmaf(qx, p.x, fmaf(qy, p.y, qz * p.z));
            if (gbase + lane == q) d = 3.0e38f;

            unsigned m = __ballot_sync(0xffffffffu, d < cm);
            while (m) {
                const int src = __ffs(m) - 1; m &= m - 1;
                const float dd = __shfl_sync(0xffffffffu, d, src);
                const int   ii = gbase + src;
                const unsigned less = __ballot_sync(0xffffffffu,
                        (v < dd) || (v == dd && vi < ii));
                const int pos = __popc(less);
                const float pv = __shfl_up_sync(0xffffffffu, v, 1);
                const int   pi = __shfl_up_sync(0xffffffffu, vi, 1);
                if (pos < 32) {
                    if (lane == pos)      { v = dd; vi = ii; }
                    else if (lane > pos)  { v = pv; vi = pi; }
                }
                cm = __shfl_sync(0xffffffffu, v, 31);
            }
        }
    }
    idx[((size_t)b * NPTS + q) * KNB + lane] = vi;
}

// =================================================================
// K2: per-point 3-layer MLP (3->64->64->128), f32x2 math, fp16 out
// =================================================================
#define SMEM_FEAT_FLOATS (192 + 64 + 4096 + 64 + 8192 + 128)
#define SMEM_FEAT_BYTES  (SMEM_FEAT_FLOATS * 4)

__global__ __launch_bounds__(128) void feat_kernel(
    const float* __restrict__ x,
    const float* __restrict__ sW0, const float* __restrict__ sb0,
    const float* __restrict__ sW1, const float* __restrict__ sb1,
    const float* __restrict__ sW2, const float* __restrict__ sb2,
    __half* __restrict__ feat, int B)
{
    extern __shared__ float sm[];
    float* w0s = sm;
    float* b0s = w0s + 192;
    float* w1s = b0s + 64;
    float* b1s = w1s + 4096;
    float* w2s = b1s + 64;
    float* b2s = w2s + 8192;

    const int s = blockIdx.y, b = blockIdx.z;
    const int tid = threadIdx.x;

    for (int i = tid; i < 192;  i += 128) w0s[i] = sW0[s * 192 + i];
    for (int i = tid; i < 64;   i += 128) { b0s[i] = sb0[s * 64 + i]; b1s[i] = sb1[s * 64 + i]; }
    for (int i = tid; i < 4096; i += 128) w1s[i] = sW1[s * 4096 + i];
    for (int i = tid; i < 8192; i += 128) w2s[i] = sW2[s * 8192 + i];
    for (int i = tid; i < 128;  i += 128) b2s[i] = sb2[s * 128 + i];
    __syncthreads();

    const int j = blockIdx.x * 128 + tid;
    const float* xb = x + (size_t)b * 3 * NPTS;
    const float px = xb[j], py = xb[NPTS + j], pz = xb[2 * NPTS + j];

    float h0[64];
#pragma unroll
    for (int o = 0; o < 64; o++) {
        float a = fmaf(w0s[o * 3 + 2], pz,
                  fmaf(w0s[o * 3 + 1], py,
                  fmaf(w0s[o * 3 + 0], px, b0s[o])));
        h0[o] = fmaxf(a, 0.0f);
    }

    ull hp[32];
#pragma unroll
    for (int c = 0; c < 32; c++) hp[c] = pack2(h0[2 * c], h0[2 * c + 1]);

    float h1[64];
#pragma unroll
    for (int o = 0; o < 64; o += 2) {
        ull a0 = 0ull, a1 = 0ull;
        const ull* r0 = (const ull*)(w1s + (o    ) * 64);
        const ull* r1 = (const ull*)(w1s + (o + 1) * 64);
#pragma unroll
        for (int c = 0; c < 32; c++) {
            a0 = ffma2(r0[c], hp[c], a0);
            a1 = ffma2(r1[c], hp[c], a1);
        }
        const float2 u0 = unpack2(a0), u1 = unpack2(a1);
        h1[o]     = fmaxf(u0.x + u0.y + b1s[o],     0.0f);
        h1[o + 1] = fmaxf(u1.x + u1.y + b1s[o + 1], 0.0f);
    }

#pragma unroll
    for (int c = 0; c < 32; c++) hp[c] = pack2(h1[2 * c], h1[2 * c + 1]);

    __half* fout = feat + ((size_t)(s * B + b) * NPTS + j) * 128;
    for (int o = 0; o < 128; o += 4) {
        ull a0 = 0ull, a1 = 0ull, a2 = 0ull, a3 = 0ull;
        const ull* r0 = (const ull*)(w2s + (size_t)(o    ) * 64);
        const ull* r1 = (const ull*)(w2s + (size_t)(o + 1) * 64);
        const ull* r2 = (const ull*)(w2s + (size_t)(o + 2) * 64);
        const ull* r3 = (const ull*)(w2s + (size_t)(o + 3) * 64);
#pragma unroll
        for (int c = 0; c < 32; c++) {
            a0 = ffma2(r0[c], hp[c], a0);
            a1 = ffma2(r1[c], hp[c], a1);
            a2 = ffma2(r2[c], hp[c], a2);
            a3 = ffma2(r3[c], hp[c], a3);
        }
        const float2 u0 = unpack2(a0), u1 = unpack2(a1);
        const float2 u2 = unpack2(a2), u3 = unpack2(a3);
        const float v0 = fmaxf(u0.x + u0.y + b2s[o],     0.0f);
        const float v1 = fmaxf(u1.x + u1.y + b2s[o + 1], 0.0f);
        const float v2 = fmaxf(u2.x + u2.y + b2s[o + 2], 0.0f);
        const float v3 = fmaxf(u3.x + u3.y + b2s[o + 3], 0.0f);
        uint32_t p0, p1;
        asm("cvt.rn.f16x2.f32 %0, %1, %2;" : "=r"(p0) : "f"(v1), "f"(v0));
        asm("cvt.rn.f16x2.f32 %0, %1, %2;" : "=r"(p1) : "f"(v3), "f"(v2));
        *(uint2*)(fout + o) = make_uint2(p0, p1);
    }
}

// =================================================================
// K3: gather-max over 32 neighbors (fp16, exact) -> pt[b][n][384]
// =================================================================
__global__ __launch_bounds__(256) void maxpool_kernel(
    const __half* __restrict__ feat, const int* __restrict__ idx,
    __half* __restrict__ pt, int B)
{
    const int s = blockIdx.y, b = blockIdx.z;
    const int tid = threadIdx.x;
    const int w = tid >> 5, lane = tid & 31;
    const int n = blockIdx.x * 8 + w;

    const int ki = idx[((size_t)b * NPTS + n) * KNB + lane];
    const __half* fb = feat + (size_t)(s * B + b) * NPTS * 128;

    __half2 m01 = __float2half2_rn(0.0f);
    __half2 m23 = __float2half2_rn(0.0f);
#pragma unroll
    for (int k = 0; k < KNB; k++) {
        const int j = __shfl_sync(0xffffffffu, ki, k);
        const uint2 vv = *(const uint2*)(fb + (size_t)j * 128 + lane * 4);
        m01 = __hmax2(m01, *(const __half2*)&vv.x);
        m23 = __hmax2(m23, *(const __half2*)&vv.y);
    }
    const size_t ofs = ((size_t)b * NPTS + n) * 384 + s * 128 + lane * 4;
    *(uint2*)(pt + ofs) = make_uint2(*(const uint32_t*)&m01, *(const uint32_t*)&m23);
}

// =================================================================
// K4: mma.sync fp16 GEMM, single fp16 plane both operands.
// cp.async 3-stage pipeline. CTA 128x128, 4 warps (2x2, warp tile
// 64x64), 128 threads, k-chunk 32, 2 CTAs/SM.
// =================================================================
#define KCH    32
#define PITCH  80
#define ATILE  (128 * PITCH)            // 10240 B
#define STG_B  (2 * ATILE)              // A|B = 20480
#define NSTG   3
#define SMEM_GEMM_BYTES (NSTG * STG_B)  // 61440

__global__ __launch_bounds__(128, 2) void gemm_mma(
    const __half* __restrict__ Wh, const float* __restrict__ bias,
    const __half* __restrict__ Xh,
    __half* __restrict__ Yh, float* __restrict__ Yf, int M, int K)
{
    extern __shared__ __align__(16) char smem[];
    const uint32_t sb = smem_u32(smem);

    const int tid = threadIdx.x, wid = tid >> 5, lane = tid & 31;
    const int wm = wid & 1, wn = wid >> 1;           // 2 x 2 warp grid
    const int m0 = blockIdx.x * 128, n0 = blockIdx.y * 128;
    const int bi = blockIdx.z;
    const size_t xrow0 = (size_t)bi * NPTS + n0;

    const uint32_t aOff = (uint32_t)(wm * 64 + (lane & 7) + ((lane >> 3) & 1) * 8) * PITCH
                        + ((lane >> 4) & 1) * 16;
    const uint32_t bOff = (uint32_t)(wn * 64 + (lane & 7) + ((lane >> 4) & 1) * 8) * PITCH
                        + ((lane >> 3) & 1) * 16;

    float acc[4][8][4];
#pragma unroll
    for (int i = 0; i < 4; i++)
#pragma unroll
        for (int j = 0; j < 8; j++)
#pragma unroll
            for (int r = 0; r < 4; r++) acc[i][j][r] = 0.0f;

    const int nch = K / KCH;

    auto issue = [&](int ch, int stg) {
        const uint32_t sbase = sb + (uint32_t)stg * STG_B;
        const int kof = ch * KCH;
#pragma unroll
        for (int r = 0; r < 4; r++) {
            const int unit = tid + r * 128;
            const int row = unit >> 2, seg = unit & 3;
            const uint32_t d = sbase + (uint32_t)row * PITCH + seg * 16;
            cp16(d,         Wh + (size_t)(m0 + row) * K + kof + seg * 8);
            cp16(d + ATILE, Xh + (xrow0 + row) * K + kof + seg * 8);
        }
        asm volatile("cp.async.commit_group;" ::: "memory");
    };

    issue(0, 0);
    if (nch > 1) issue(1, 1);

    for (int ch = 0; ch < nch; ch++) {
        if (ch + 1 < nch) asm volatile("cp.async.wait_group 1;" ::: "memory");
        else              asm volatile("cp.async.wait_group 0;" ::: "memory");
        __syncthreads();

        if (ch + 2 < nch) issue(ch + 2, (ch + 2) % NSTG);

        const uint32_t aT = sb + (uint32_t)(ch % NSTG) * STG_B + aOff;
        const uint32_t bT = sb + (uint32_t)(ch % NSTG) * STG_B + ATILE + bOff;
#pragma unroll
        for (int ks = 0; ks < 2; ks++) {
            const uint32_t kso = ks * 32;
            uint32_t bh[8][2];
#pragma unroll
            for (int pr = 0; pr < 4; pr++) {
                const uint32_t bo = bT + (uint32_t)pr * (16 * PITCH) + kso;
                ldsm4(bh[pr * 2][0], bh[pr * 2][1], bh[pr * 2 + 1][0], bh[pr * 2 + 1][1], bo);
            }
#pragma unroll
            for (int mi = 0; mi < 4; mi++) {
                uint32_t ah[4];
                const uint32_t ao = aT + (uint32_t)mi * (16 * PITCH) + kso;
                ldsm4(ah[0], ah[1], ah[2], ah[3], ao);
#pragma unroll
                for (int ni = 0; ni < 8; ni++)
                    mma_f16(acc[mi][ni], ah, bh[ni]);
            }
        }
    }

    // epilogue
    const int g = lane >> 2, t2 = (lane & 3) * 2;
#pragma unroll
    for (int mi = 0; mi < 4; mi++) {
        const int mlo = m0 + wm * 64 + mi * 16 + g;
        const float bv0 = bias[mlo], bv1 = bias[mlo + 8];
#pragma unroll
        for (int ni = 0; ni < 8; ni++) {
            const int n = n0 + wn * 64 + ni * 8 + t2;
            const size_t r0 = ((size_t)bi * NPTS + n) * M;
            const size_t r1 = r0 + M;
            const float v0 = fmaxf(acc[mi][ni][0] + bv0, 0.0f);
            const float v1 = fmaxf(acc[mi][ni][1] + bv0, 0.0f);
            const float v2 = fmaxf(acc[mi][ni][2] + bv1, 0.0f);
            const float v3 = fmaxf(acc[mi][ni][3] + bv1, 0.0f);
            if (Yh) {
                Yh[r0 + mlo]     = __float2half_rn(v0);
                Yh[r1 + mlo]     = __float2half_rn(v1);
                Yh[r0 + mlo + 8] = __float2half_rn(v2);
                Yh[r1 + mlo + 8] = __float2half_rn(v3);
            } else {
                Yf[r0 + mlo]     = v0;
                Yf[r1 + mlo]     = v1;
                Yf[r0 + mlo + 8] = v2;
                Yf[r1 + mlo + 8] = v3;
            }
        }
    }
}

// =================================================================
// rowmax on gf (fp16), two-phase
// =================================================================
__global__ __launch_bounds__(256) void rowmax_part(const __half* __restrict__ gf,
                                                   float* __restrict__ part)
{
    const int c = blockIdx.x * 256 + threadIdx.x;
    const int ns = blockIdx.y, b = blockIdx.z;
    const size_t base = ((size_t)b * NPTS + ns * 256) * 1024 + c;
    __half m0 = __float2half_rn(0.0f), m1 = m0, m2 = m0, m3 = m0;
#pragma unroll 4
    for (int n = 0; n < 256; n += 4) {
        m0 = __hmax(m0, gf[base + (size_t)(n    ) * 1024]);
        m1 = __hmax(m1, gf[base + (size_t)(n + 1) * 1024]);
        m2 = __hmax(m2, gf[base + (size_t)(n + 2) * 1024]);
        m3 = __hmax(m3, gf[base + (size_t)(n + 3) * 1024]);
    }
    part[(size_t)(b * 16 + ns) * 1024 + c] =
        __half2float(__hmax(__hmax(m0, m1), __hmax(m2, m3)));
}

__global__ __launch_bounds__(256) void rowmax_fin(const float* __restrict__ part,
                                                  float* __restrict__ out)
{
    const int c = blockIdx.x * 256 + threadIdx.x;
    const int b = blockIdx.y;
    float m = -3.0e38f;
#pragma unroll
    for (int i = 0; i < 16; i++)
        m = fmaxf(m, part[(size_t)(b * 16 + i) * 1024 + c]);
    out[(size_t)b * 1024 + c] = m;
}

// =================================================================
// transpose msf_t[b][n][128] -> out[b][128][n]
// =================================================================
__global__ void transpose_msf(const float* __restrict__ in, float* __restrict__ out)
{
    __shared__ float t[32][33];
    const int b = blockIdx.z;
    const int n0 = blockIdx.x * 32, c0 = blockIdx.y * 32;
    const int tx = threadIdx.x, ty = threadIdx.y;
#pragma unroll
    for (int r = 0; r < 32; r += 8)
        t[ty + r][tx] = in[(size_t)((size_t)b * NPTS + n0 + ty + r) * 128 + c0 + tx];
    __syncthreads();
#pragma unroll
    for (int r = 0; r < 32; r += 8)
        out[(size_t)((size_t)b * 128 + c0 + ty + r) * NPTS + n0 + tx] = t[tx][ty + r];
}

// =================================================================
extern "C" void kernel_launch(void* const* d_in, const int* in_sizes, int n_in,
                              void* d_out, int out_size)
{
    const float* x   = (const float*)d_in[0];
    const float* sW0 = (const float*)d_in[1];
    const float* sb0 = (const float*)d_in[2];
    const float* sW1 = (const float*)d_in[3];
    const float* sb1 = (const float*)d_in[4];
    const float* sW2 = (const float*)d_in[5];
    const float* sb2 = (const float*)d_in[6];
    const float* gW0 = (const float*)d_in[7];
    const float* gb0 = (const float*)d_in[8];
    const float* gW1 = (const float*)d_in[9];
    const float* gb1 = (const float*)d_in[10];
    const float* mW0 = (const float*)d_in[11];
    const float* mb0 = (const float*)d_in[12];
    const float* mW1 = (const float*)d_in[13];
    const float* mb1 = (const float*)d_in[14];

    const int B = in_sizes[0] / (3 * NPTS);
    float* out = (float*)d_out;

    void *p_idx, *p_feat, *p_pt, *p_g0, *p_gf, *p_m0, *p_msf, *p_part, *p_wh;
    cudaGetSymbolAddress(&p_idx,  g_idx);
    cudaGetSymbolAddress(&p_feat, g_feat);
    cudaGetSymbolAddress(&p_pt,   g_pt);
    cudaGetSymbolAddress(&p_g0,   g_gf0);
    cudaGetSymbolAddress(&p_gf,   g_gf);
    cudaGetSymbolAddress(&p_m0,   g_msf0);
    cudaGetSymbolAddress(&p_msf,  g_msf_t);
    cudaGetSymbolAddress(&p_part, g_part);
    cudaGetSymbolAddress(&p_wh,   g_w_h);

    __half* wh = (__half*)p_wh;

    cudaFuncSetAttribute(feat_kernel,
                         cudaFuncAttributeMaxDynamicSharedMemorySize, SMEM_FEAT_BYTES);
    cudaFuncSetAttribute(gemm_mma,
                         cudaFuncAttributeMaxDynamicSharedMemorySize, SMEM_GEMM_BYTES);

    // 0) weights -> fp16
    split_all<<<640, 256>>>(gW0, gW1, mW0, mW1, wh);

    // 1) KNN
    knn_kernel<<<dim3(NPTS / 8, B), 256>>>(x, (int*)p_idx);

    // 2) per-point MLP features (fp16 plane)
    feat_kernel<<<dim3(NPTS / 128, 3, B), 128, SMEM_FEAT_BYTES>>>(
        x, sW0, sb0, sW1, sb1, sW2, sb2, (__half*)p_feat, B);

    // 3) gather-max -> pt[b][n][384]
    maxpool_kernel<<<dim3(NPTS / 8, 3, B), 256>>>(
        (const __half*)p_feat, (const int*)p_idx, (__half*)p_pt, B);

    // 4) gf0 = relu(gW0 @ point)   M=256,K=384
    gemm_mma<<<dim3(2, NPTS / 128, B), 128, SMEM_GEMM_BYTES>>>(
        wh + OFF_G0, gb0, (const __half*)p_pt, (__half*)p_g0, nullptr, 256, 384);

    // 5) gf = relu(gW1 @ gf0)      M=1024,K=256
    gemm_mma<<<dim3(8, NPTS / 128, B), 128, SMEM_GEMM_BYTES>>>(
        wh + OFF_G1, gb1, (const __half*)p_g0, (__half*)p_gf, nullptr, 1024, 256);

    // 6) global_feature -> d_out[0 : B*1024]
    rowmax_part<<<dim3(4, 16, B), 256>>>((const __half*)p_gf, (float*)p_part);
    rowmax_fin<<<dim3(4, B), 256>>>((const float*)p_part, out);

    // 7) msf0 = relu(mW0 @ gf)     M=256,K=1024
    gemm_mma<<<dim3(2, NPTS / 128, B), 128, SMEM_GEMM_BYTES>>>(
        wh + OFF_M0, mb0, (const __half*)p_gf, (__half*)p_m0, nullptr, 256, 1024);

    // 8) msf = relu(mW1 @ msf0)    M=128,K=256 (fp32 out)
    gemm_mma<<<dim3(1, NPTS / 128, B), 128, SMEM_GEMM_BYTES>>>(
        wh + OFF_M1, mb1, (const __half*)p_m0, nullptr, (float*)p_msf, 128, 256);

    // 9) transpose -> d_out[B*1024 : ] as [B,128,N]
    transpose_msf<<<dim3(NPTS / 32, 128 / 32, B), dim3(32, 8)>>>(
        (const float*)p_msf, out + (size_t)B * 1024);
}